// round 1
// baseline (speedup 1.0000x reference)
#include <cuda_runtime.h>
#include <cstdint>

#define NN 30000
#define EE 250000
#define IN_F 512
#define HID_F 256
#define OUT_F 128

// ---------------- scratch (static device globals; no allocs) ----------------
__device__ float g_y0[(size_t)NN * HID_F];
__device__ float g_y1[(size_t)NN * HID_F];
__device__ float g_y2[(size_t)NN * HID_F];
__device__ float g_y3[(size_t)NN * HID_F];
__device__ float g_hd[(size_t)NN * HID_F];
__device__ float g_hp[(size_t)NN * HID_F];
__device__ float g_zd[(size_t)NN * 3 * OUT_F];
__device__ float g_zp[(size_t)NN * 3 * OUT_F];
__device__ float g_rout[16 * NN];
__device__ float g_rin[16 * NN];
__device__ float g_wsum[8];
__device__ float g_beta[8];

// ---------------- small helpers ----------------
typedef unsigned long long u64;

__device__ __forceinline__ u64 pk2(float x, float y) {
    u64 r;
    asm("mov.b64 %0, {%1, %2};" : "=l"(r) : "r"(__float_as_uint(x)), "r"(__float_as_uint(y)));
    return r;
}
__device__ __forceinline__ void fma2(u64& c, u64 a, u64 b) {
    asm("fma.rn.f32x2 %0, %1, %2, %3;" : "=l"(c) : "l"(a), "l"(b), "l"(c));
}
__device__ __forceinline__ float2 upk2(u64 v) {
    unsigned lo, hi;
    asm("mov.b64 {%0, %1}, %2;" : "=r"(lo), "=r"(hi) : "l"(v));
    return make_float2(__uint_as_float(lo), __uint_as_float(hi));
}

// ---------------- utility kernels ----------------
__global__ void k_zero(float* __restrict__ p, int n) {
    int i = blockIdx.x * blockDim.x + threadIdx.x;
    if (i < n) p[i] = 0.f;
}

__global__ void k_count(const int* __restrict__ s, const int* __restrict__ d,
                        float* __restrict__ rout, float* __restrict__ rin) {
    int i = blockIdx.x * blockDim.x + threadIdx.x;
    if (i >= 16 * EE) return;
    int cr = i / EE;
    atomicAdd(&rout[cr * NN + s[i]], 1.f);
    atomicAdd(&rin [cr * NN + d[i]], 1.f);
}

__global__ void k_rsqrt(float* __restrict__ p, int n) {
    int i = blockIdx.x * blockDim.x + threadIdx.x;
    if (i < n) p[i] = rsqrtf(fmaxf(p[i], 1.f));
}

// acc[n*stride + colOff + f] = ba[f] + bb[f]
__global__ void k_bias2(float* __restrict__ acc, const float* __restrict__ ba,
                        const float* __restrict__ bb, int F, int stride, int colOff) {
    int i = blockIdx.x * blockDim.x + threadIdx.x;
    if (i >= NN * F) return;
    int n = i / F, f = i - n * F;
    acc[(size_t)n * stride + colOff + f] = ba[f] + bb[f];
}

__global__ void k_relu(float* __restrict__ p, int F, int stride, int colOff) {
    int i = blockIdx.x * blockDim.x + threadIdx.x;
    if (i >= NN * F) return;
    int n = i / F, f = i - n * F;
    size_t idx = (size_t)n * stride + colOff + f;
    p[idx] = fmaxf(p[idx], 0.f);
}

// ---------------- SGEMM: C[M,Nout] = A[M,K] @ B[K,Nout], fp32, FFMA2 ----------------
#define BM 128
#define BN 64
#define BK 16

__global__ void __launch_bounds__(256) k_gemm(const float* __restrict__ A,
                                              const float* __restrict__ B,
                                              float* __restrict__ C,
                                              int M, int K, int Nout) {
    __shared__ float As[BK][BM];
    __shared__ float Bs[BK][BN];
    int tid = threadIdx.x;
    int bm = blockIdx.y * BM;
    int bn = blockIdx.x * BN;
    int tx = tid & 15, ty = tid >> 4;   // ty: 8-row group, tx: 4-col group

    u64 cc[8][2];
#pragma unroll
    for (int i = 0; i < 8; ++i) { cc[i][0] = 0ull; cc[i][1] = 0ull; }

    int a_m = tid >> 2;            // 0..63
    int a_k = (tid & 3) << 2;      // 0,4,8,12
    int b_k = tid >> 4;            // 0..15
    int b_n = (tid & 15) << 2;     // 0..60

    for (int k0 = 0; k0 < K; k0 += BK) {
#pragma unroll
        for (int h = 0; h < 2; ++h) {
            int m = bm + a_m + h * 64;
            float4 v = make_float4(0.f, 0.f, 0.f, 0.f);
            if (m < M) v = *(const float4*)(A + (size_t)m * K + k0 + a_k);
            As[a_k + 0][a_m + h * 64] = v.x;
            As[a_k + 1][a_m + h * 64] = v.y;
            As[a_k + 2][a_m + h * 64] = v.z;
            As[a_k + 3][a_m + h * 64] = v.w;
        }
        *(float4*)&Bs[b_k][b_n] = *(const float4*)(B + (size_t)(k0 + b_k) * Nout + bn + b_n);
        __syncthreads();

#pragma unroll
        for (int kk = 0; kk < BK; ++kk) {
            float4 a0 = *(const float4*)&As[kk][ty * 8];
            float4 a1 = *(const float4*)&As[kk][ty * 8 + 4];
            float4 b  = *(const float4*)&Bs[kk][tx * 4];
            u64 b01 = pk2(b.x, b.y);
            u64 b23 = pk2(b.z, b.w);
            float av[8] = {a0.x, a0.y, a0.z, a0.w, a1.x, a1.y, a1.z, a1.w};
#pragma unroll
            for (int i = 0; i < 8; ++i) {
                u64 a2 = pk2(av[i], av[i]);
                fma2(cc[i][0], a2, b01);
                fma2(cc[i][1], a2, b23);
            }
        }
        __syncthreads();
    }

#pragma unroll
    for (int i = 0; i < 8; ++i) {
        int m = bm + ty * 8 + i;
        if (m < M) {
            float2 lo = upk2(cc[i][0]);
            float2 hi = upk2(cc[i][1]);
            float4 v = make_float4(lo.x, lo.y, hi.x, hi.y);
            *(float4*)(C + (size_t)m * Nout + bn + tx * 4) = v;
        }
    }
}

// ------------- edge scatter: acc[d, colOff:colOff+F] += rout[s]*rin[d] * y[s, :] -------------
template <int F>
__global__ void __launch_bounds__(256) k_scatter(const float* __restrict__ y,
                                                 const int* __restrict__ src,
                                                 const int* __restrict__ dst,
                                                 const float* __restrict__ rout,
                                                 const float* __restrict__ rin,
                                                 float* __restrict__ acc,
                                                 int stride, int colOff) {
    constexpr int TPE = F / 4;       // threads per edge (float4 lanes)
    constexpr int EPB = 256 / TPE;   // edges per block
    int e = blockIdx.x * EPB + threadIdx.x / TPE;
    if (e >= EE) return;
    int l = threadIdx.x % TPE;
    int s = __ldg(&src[e]);
    int d = __ldg(&dst[e]);
    float coef = rout[s] * rin[d];
    float4 v = *(const float4*)(y + (size_t)s * F + l * 4);
    float* p = acc + (size_t)d * stride + colOff + l * 4;
    asm volatile("red.global.add.v4.f32 [%0], {%1, %2, %3, %4};"
                 :: "l"(p), "f"(v.x * coef), "f"(v.y * coef), "f"(v.z * coef), "f"(v.w * coef)
                 : "memory");
}

// ------------- semantic attention: w[n,k] = tanh(z[n,k,:]@Wp + bp) . q, sum over n -------------
__global__ void k_attn(const float* __restrict__ zd, const float* __restrict__ zp,
                       const float* __restrict__ Wp, const float* __restrict__ bp,
                       const float* __restrict__ q, float* __restrict__ wsum) {
    __shared__ float sb[6];
    if (threadIdx.x < 6) sb[threadIdx.x] = 0.f;
    __syncthreads();

    int gw = (blockIdx.x * blockDim.x + threadIdx.x) >> 5;
    int lane = threadIdx.x & 31;
    bool valid = gw < 2 * NN * 3;
    int t = 0, n = 0, k = 0;
    float s = 0.f;
    if (valid) {
        t = gw / (NN * 3);
        int r = gw - t * NN * 3;
        n = r / 3;
        k = r - n * 3;
        const float* z = (t ? zp : zd) + (size_t)n * (3 * OUT_F) + k * OUT_F;
        int j0 = lane * 4;
        float4 acc = *(const float4*)(bp + j0);
#pragma unroll 4
        for (int i = 0; i < OUT_F; i += 4) {
            float4 zi = *(const float4*)(z + i);
            const float* w = Wp + (size_t)i * OUT_F + j0;
            float4 w0 = *(const float4*)(w);
            acc.x += zi.x * w0.x; acc.y += zi.x * w0.y; acc.z += zi.x * w0.z; acc.w += zi.x * w0.w;
            float4 w1 = *(const float4*)(w + OUT_F);
            acc.x += zi.y * w1.x; acc.y += zi.y * w1.y; acc.z += zi.y * w1.z; acc.w += zi.y * w1.w;
            float4 w2 = *(const float4*)(w + 2 * OUT_F);
            acc.x += zi.z * w2.x; acc.y += zi.z * w2.y; acc.z += zi.z * w2.z; acc.w += zi.z * w2.w;
            float4 w3 = *(const float4*)(w + 3 * OUT_F);
            acc.x += zi.w * w3.x; acc.y += zi.w * w3.y; acc.z += zi.w * w3.z; acc.w += zi.w * w3.w;
        }
        float4 qv = *(const float4*)(q + j0);
        s = tanhf(acc.x) * qv.x + tanhf(acc.y) * qv.y + tanhf(acc.z) * qv.z + tanhf(acc.w) * qv.w;
    }
#pragma unroll
    for (int o = 16; o; o >>= 1) s += __shfl_down_sync(0xffffffffu, s, o);
    if (valid && lane == 0) atomicAdd(&sb[t * 3 + k], s);
    __syncthreads();
    if (threadIdx.x < 6 && sb[threadIdx.x] != 0.f) atomicAdd(&wsum[threadIdx.x], sb[threadIdx.x]);
}

__global__ void k_beta(const float* __restrict__ wsum, float* __restrict__ beta,
                       float* __restrict__ outBeta) {
    if (threadIdx.x != 0 || blockIdx.x != 0) return;
    for (int t = 0; t < 2; ++t) {
        float w0 = wsum[t * 3 + 0] / (float)NN;
        float w1 = wsum[t * 3 + 1] / (float)NN;
        float w2 = wsum[t * 3 + 2] / (float)NN;
        float m = fmaxf(w0, fmaxf(w1, w2));
        float e0 = expf(w0 - m), e1 = expf(w1 - m), e2 = expf(w2 - m);
        float inv = 1.f / (e0 + e1 + e2);
        beta[t * 3 + 0] = e0 * inv; outBeta[t * 3 + 0] = e0 * inv;
        beta[t * 3 + 1] = e1 * inv; outBeta[t * 3 + 1] = e1 * inv;
        beta[t * 3 + 2] = e2 * inv; outBeta[t * 3 + 2] = e2 * inv;
    }
}

__global__ void k_combine(const float* __restrict__ zd, const float* __restrict__ zp,
                          const float* __restrict__ beta, float* __restrict__ out) {
    int i = blockIdx.x * blockDim.x + threadIdx.x;
    if (i >= 2 * NN * OUT_F) return;
    int t = i / (NN * OUT_F);
    int r = i - t * NN * OUT_F;
    int n = r / OUT_F, f = r - n * OUT_F;
    const float* z = (t ? zp : zd) + (size_t)n * (3 * OUT_F) + f;
    const float* b = beta + t * 3;
    out[i] = b[0] * z[0] + b[1] * z[OUT_F] + b[2] * z[2 * OUT_F];
}

// ---------------- host orchestration ----------------
extern "C" void kernel_launch(void* const* d_in, const int* in_sizes, int n_in,
                              void* d_out, int out_size) {
    const float* xd  = (const float*)d_in[0];
    const float* xp  = (const float*)d_in[1];
    const int*   src = (const int*)  d_in[2];
    const int*   dst = (const int*)  d_in[3];
    const float* W1  = (const float*)d_in[4];
    const float* b1  = (const float*)d_in[5];
    const float* W2  = (const float*)d_in[6];
    const float* b2  = (const float*)d_in[7];
    const float* Wpm = (const float*)d_in[8];
    const float* bp  = (const float*)d_in[9];
    const float* q   = (const float*)d_in[10];
    float* out = (float*)d_out;

    float *y[4], *hd, *hp, *zd, *zp, *rout, *rin, *wsum, *beta;
    cudaGetSymbolAddress((void**)&y[0], g_y0);
    cudaGetSymbolAddress((void**)&y[1], g_y1);
    cudaGetSymbolAddress((void**)&y[2], g_y2);
    cudaGetSymbolAddress((void**)&y[3], g_y3);
    cudaGetSymbolAddress((void**)&hd,   g_hd);
    cudaGetSymbolAddress((void**)&hp,   g_hp);
    cudaGetSymbolAddress((void**)&zd,   g_zd);
    cudaGetSymbolAddress((void**)&zp,   g_zp);
    cudaGetSymbolAddress((void**)&rout, g_rout);
    cudaGetSymbolAddress((void**)&rin,  g_rin);
    cudaGetSymbolAddress((void**)&wsum, g_wsum);
    cudaGetSymbolAddress((void**)&beta, g_beta);

    const int T = 256;

    // degrees for all (channel, relation) pairs
    k_zero<<<(16 * NN + T - 1) / T, T>>>(rout, 16 * NN);
    k_zero<<<(16 * NN + T - 1) / T, T>>>(rin, 16 * NN);
    k_count<<<(16 * EE + T - 1) / T, T>>>(src, dst, rout, rin);
    k_rsqrt<<<(16 * NN + T - 1) / T, T>>>(rout, 16 * NN);
    k_rsqrt<<<(16 * NN + T - 1) / T, T>>>(rin, 16 * NN);

    const int chans[3] = {0, 2, 3};
    const int mblocks = (NN + BM - 1) / BM;

    for (int ci = 0; ci < 3; ++ci) {
        int c = chans[ci];

        // ---- layer 1: y_r = x_src @ W1[c][r] (unscaled) ----
        const float* xin[4] = {xd, xd, xp, xp};
        for (int r = 0; r < 4; ++r)
            k_gemm<<<dim3(HID_F / BN, mblocks), 256>>>(
                xin[r], W1 + (size_t)(c * 4 + r) * IN_F * HID_F, y[r], NN, IN_F, HID_F);

        k_bias2<<<(NN * HID_F + T - 1) / T, T>>>(hd, b1 + (c * 4 + 0) * HID_F,
                                                 b1 + (c * 4 + 2) * HID_F, HID_F, HID_F, 0);
        k_bias2<<<(NN * HID_F + T - 1) / T, T>>>(hp, b1 + (c * 4 + 1) * HID_F,
                                                 b1 + (c * 4 + 3) * HID_F, HID_F, HID_F, 0);
        for (int r = 0; r < 4; ++r) {
            int cr = c * 4 + r;
            float* accp = (r == 0 || r == 2) ? hd : hp;
            k_scatter<HID_F><<<EE / (256 / (HID_F / 4)), 256>>>(
                y[r], src + (size_t)cr * EE, dst + (size_t)cr * EE,
                rout + cr * NN, rin + cr * NN, accp, HID_F, 0);
        }
        k_relu<<<(NN * HID_F + T - 1) / T, T>>>(hd, HID_F, HID_F, 0);
        k_relu<<<(NN * HID_F + T - 1) / T, T>>>(hp, HID_F, HID_F, 0);

        // ---- layer 2: y_r = h_src @ W2[c][r] ----
        const float* hin[4] = {hd, hd, hp, hp};
        for (int r = 0; r < 4; ++r)
            k_gemm<<<dim3(OUT_F / BN, mblocks), 256>>>(
                hin[r], W2 + (size_t)(c * 4 + r) * HID_F * OUT_F, y[r], NN, HID_F, OUT_F);

        k_bias2<<<(NN * OUT_F + T - 1) / T, T>>>(zd, b2 + (c * 4 + 0) * OUT_F,
                                                 b2 + (c * 4 + 2) * OUT_F, OUT_F, 3 * OUT_F, ci * OUT_F);
        k_bias2<<<(NN * OUT_F + T - 1) / T, T>>>(zp, b2 + (c * 4 + 1) * OUT_F,
                                                 b2 + (c * 4 + 3) * OUT_F, OUT_F, 3 * OUT_F, ci * OUT_F);
        for (int r = 0; r < 4; ++r) {
            int cr = c * 4 + r;
            float* accp = (r == 0 || r == 2) ? zd : zp;
            k_scatter<OUT_F><<<EE / (256 / (OUT_F / 4)), 256>>>(
                y[r], src + (size_t)cr * EE, dst + (size_t)cr * EE,
                rout + cr * NN, rin + cr * NN, accp, 3 * OUT_F, ci * OUT_F);
        }
        k_relu<<<(NN * OUT_F + T - 1) / T, T>>>(zd, OUT_F, 3 * OUT_F, ci * OUT_F);
        k_relu<<<(NN * OUT_F + T - 1) / T, T>>>(zp, OUT_F, 3 * OUT_F, ci * OUT_F);
    }

    // ---- semantic attention ----
    k_zero<<<1, 32>>>(wsum, 8);
    int warps = 2 * NN * 3;
    k_attn<<<(warps * 32 + 255) / 256, 256>>>(zd, zp, Wpm, bp, q, wsum);
    k_beta<<<1, 1>>>(wsum, beta, out + (size_t)2 * NN * OUT_F);
    k_combine<<<(2 * NN * OUT_F + T - 1) / T, T>>>(zd, zp, beta, out);
}

// round 2
// speedup vs baseline: 1.1016x; 1.1016x over previous
#include <cuda_runtime.h>
#include <cstdint>

#define NN 30000
#define EE 250000
#define IN_F 512
#define HID_F 256
#define OUT_F 128

typedef unsigned long long u64;

// ---------------- scratch (static device globals; no allocs) ----------------
__device__ float g_y[(size_t)4 * NN * HID_F];   // per-relation GEMM outputs / attn scratch
__device__ float g_hd[(size_t)NN * HID_F];
__device__ float g_hp[(size_t)NN * HID_F];
__device__ float g_zd[(size_t)NN * 3 * OUT_F];
__device__ float g_zp[(size_t)NN * 3 * OUT_F];
__device__ float g_rout[16 * NN];
__device__ float g_rin[16 * NN];
__device__ float g_wsum[8];
__device__ float g_beta[8];

// ---------------- helpers ----------------
__device__ __forceinline__ void fma2(u64& c, u64 a, u64 b) {
    asm("fma.rn.f32x2 %0, %1, %2, %3;" : "=l"(c) : "l"(a), "l"(b), "l"(c));
}
__device__ __forceinline__ float2 upk2(u64 v) {
    unsigned lo, hi;
    asm("mov.b64 {%0, %1}, %2;" : "=r"(lo), "=r"(hi) : "l"(v));
    return make_float2(__uint_as_float(lo), __uint_as_float(hi));
}

// ---------------- utility kernels ----------------
__global__ void k_zero(float* __restrict__ p, int n) {
    int i = blockIdx.x * blockDim.x + threadIdx.x;
    if (i < n) p[i] = 0.f;
}

__global__ void k_count(const int* __restrict__ s, const int* __restrict__ d,
                        float* __restrict__ rout, float* __restrict__ rin) {
    int i = blockIdx.x * blockDim.x + threadIdx.x;
    if (i >= 16 * EE) return;
    int cr = i / EE;
    atomicAdd(&rout[cr * NN + s[i]], 1.f);
    atomicAdd(&rin [cr * NN + d[i]], 1.f);
}

__global__ void k_rsqrt(float* __restrict__ p, int n) {
    int i = blockIdx.x * blockDim.x + threadIdx.x;
    if (i < n) p[i] = rsqrtf(fmaxf(p[i], 1.f));
}

__global__ void k_bias2(float* __restrict__ acc, const float* __restrict__ ba,
                        const float* __restrict__ bb, int F, int stride, int colOff) {
    int i = blockIdx.x * blockDim.x + threadIdx.x;
    if (i >= NN * F) return;
    int n = i / F, f = i - n * F;
    acc[(size_t)n * stride + colOff + f] = ba[f] + bb[f];
}

__global__ void k_relu(float* __restrict__ p, int F, int stride, int colOff) {
    int i = blockIdx.x * blockDim.x + threadIdx.x;
    if (i >= NN * F) return;
    int n = i / F, f = i - n * F;
    size_t idx = (size_t)n * stride + colOff + f;
    p[idx] = fmaxf(p[idx], 0.f);
}

// ---------------- SGEMM core: 256x64 tile, BK=16, FFMA2 with pre-paired smem ----------------
// Thread tile: 16 m (8 pairs) x 4 n. A pairs via broadcast LDS.128; B duplicated float2 in smem.
#define BM 256
#define BN 64
#define BK 16

__device__ __forceinline__ void gemm_core(
    const float* __restrict__ A, const float* __restrict__ B, float* __restrict__ C,
    int M, int K, int N, int bm, int bn)
{
    __shared__ float  As[2][BK][BM];    // 32 KB
    __shared__ float2 Bs[2][BK][BN];    // 16 KB, duplicated pairs

    const int tid = threadIdx.x;
    const int tx = tid & 15;            // n group
    const int ty = tid >> 4;            // m group (0..15), 16 m each
    // global-load indices
    const int am  = tid >> 1;           // 0..127 (two m per thread: am, am+128)
    const int akh = (tid & 1) << 3;     // 0 or 8 (k half)
    const int bkr = tid >> 4;           // 0..15
    const int bn4 = (tid & 15) << 2;    // 0..60

    u64 acc[8][4];
#pragma unroll
    for (int i = 0; i < 8; ++i)
#pragma unroll
        for (int j = 0; j < 4; ++j) acc[i][j] = 0ull;

    float4 va[4], vb;
    // prefetch chunk 0
    {
#pragma unroll
        for (int h = 0; h < 2; ++h) {
            int m = bm + am + 128 * h;
            if (m < M) {
                va[2*h]   = *(const float4*)(A + (size_t)m * K + akh);
                va[2*h+1] = *(const float4*)(A + (size_t)m * K + akh + 4);
            } else {
                va[2*h] = make_float4(0.f,0.f,0.f,0.f);
                va[2*h+1] = make_float4(0.f,0.f,0.f,0.f);
            }
        }
        vb = *(const float4*)(B + (size_t)bkr * N + bn + bn4);
    }

    const int nk = K >> 4;
    for (int kc = 0; kc < nk; ++kc) {
        const int buf = kc & 1;
        // store prefetched chunk into smem[buf]
#pragma unroll
        for (int h = 0; h < 2; ++h) {
            int mloc = am + 128 * h;
            float4 v0 = va[2*h], v1 = va[2*h+1];
            As[buf][akh+0][mloc] = v0.x; As[buf][akh+1][mloc] = v0.y;
            As[buf][akh+2][mloc] = v0.z; As[buf][akh+3][mloc] = v0.w;
            As[buf][akh+4][mloc] = v1.x; As[buf][akh+5][mloc] = v1.y;
            As[buf][akh+6][mloc] = v1.z; As[buf][akh+7][mloc] = v1.w;
        }
        *(float4*)&Bs[buf][bkr][bn4]     = make_float4(vb.x, vb.x, vb.y, vb.y);
        *(float4*)&Bs[buf][bkr][bn4 + 2] = make_float4(vb.z, vb.z, vb.w, vb.w);
        __syncthreads();

        if (kc + 1 < nk) {
            int k0 = (kc + 1) << 4;
#pragma unroll
            for (int h = 0; h < 2; ++h) {
                int m = bm + am + 128 * h;
                if (m < M) {
                    va[2*h]   = *(const float4*)(A + (size_t)m * K + k0 + akh);
                    va[2*h+1] = *(const float4*)(A + (size_t)m * K + k0 + akh + 4);
                } else {
                    va[2*h] = make_float4(0.f,0.f,0.f,0.f);
                    va[2*h+1] = make_float4(0.f,0.f,0.f,0.f);
                }
            }
            vb = *(const float4*)(B + (size_t)(k0 + bkr) * N + bn + bn4);
        }

        // compute from smem[buf]
#pragma unroll
        for (int kk = 0; kk < BK; ++kk) {
            ulonglong2 aa0 = *(const ulonglong2*)&As[buf][kk][ty * 16];
            ulonglong2 aa1 = *(const ulonglong2*)&As[buf][kk][ty * 16 + 4];
            ulonglong2 aa2 = *(const ulonglong2*)&As[buf][kk][ty * 16 + 8];
            ulonglong2 aa3 = *(const ulonglong2*)&As[buf][kk][ty * 16 + 12];
            const ulonglong2* brow = (const ulonglong2*)&Bs[buf][kk][0];
            ulonglong2 bb0 = brow[tx];
            ulonglong2 bb1 = brow[tx + 16];
            u64 a[8] = {aa0.x, aa0.y, aa1.x, aa1.y, aa2.x, aa2.y, aa3.x, aa3.y};
            u64 bv[4] = {bb0.x, bb0.y, bb1.x, bb1.y};
#pragma unroll
            for (int i = 0; i < 8; ++i) {
#pragma unroll
                for (int j = 0; j < 4; ++j) fma2(acc[i][j], a[i], bv[j]);
            }
        }
        __syncthreads();
    }

    // epilogue: acc[i][j] lanes = (C[m0][n], C[m1][n]); recombine to row-major float2
#pragma unroll
    for (int i = 0; i < 8; ++i) {
        int m0 = bm + ty * 16 + 2 * i;
        int m1 = m0 + 1;
#pragma unroll
        for (int g = 0; g < 2; ++g) {
            float2 p = upk2(acc[i][2 * g]);       // n = base
            float2 q = upk2(acc[i][2 * g + 1]);   // n = base+1
            int n = bn + tx * 2 + 32 * g;
            if (m0 < M) *(float2*)(C + (size_t)m0 * N + n) = make_float2(p.x, q.x);
            if (m1 < M) *(float2*)(C + (size_t)m1 * N + n) = make_float2(p.y, q.y);
        }
    }
}

// all 4 relations of one layer in one launch: r<2 uses A0, else A1
template <int KK, int NOUT>
__global__ void __launch_bounds__(256, 2) k_gemm_quad(
    const float* __restrict__ A0, const float* __restrict__ A1,
    const float* __restrict__ W, float* __restrict__ Y)
{
    constexpr int nbn = NOUT / BN;
    int r  = blockIdx.x / nbn;
    int bn = (blockIdx.x - r * nbn) * BN;
    gemm_core((r < 2) ? A0 : A1, W + (size_t)r * KK * NOUT,
              Y + (size_t)r * NN * NOUT, NN, KK, NOUT, blockIdx.y * BM, bn);
}

__global__ void __launch_bounds__(256, 2) k_gemm_one(
    const float* __restrict__ A, const float* __restrict__ B, float* __restrict__ C,
    int M, int K, int N)
{
    gemm_core(A, B, C, M, K, N, blockIdx.y * BM, blockIdx.x * BN);
}

// ------------- edge scatter: acc[d, colOff:colOff+F] += rout[s]*rin[d] * y[s, :] -------------
template <int F>
__global__ void __launch_bounds__(256) k_scatter(const float* __restrict__ y,
                                                 const int* __restrict__ src,
                                                 const int* __restrict__ dst,
                                                 const float* __restrict__ rout,
                                                 const float* __restrict__ rin,
                                                 float* __restrict__ acc,
                                                 int stride, int colOff) {
    constexpr int TPE = F / 4;
    constexpr int EPB = 256 / TPE;
    int e = blockIdx.x * EPB + threadIdx.x / TPE;
    if (e >= EE) return;
    int l = threadIdx.x % TPE;
    int s = __ldg(&src[e]);
    int d = __ldg(&dst[e]);
    float coef = rout[s] * rin[d];
    float4 v = *(const float4*)(y + (size_t)s * F + l * 4);
    float* p = acc + (size_t)d * stride + colOff + l * 4;
    asm volatile("red.global.add.v4.f32 [%0], {%1, %2, %3, %4};"
                 :: "l"(p), "f"(v.x * coef), "f"(v.y * coef), "f"(v.z * coef), "f"(v.w * coef)
                 : "memory");
}

// ------------- attention reduction: wsum[t*3+k] += tanh(T[row]+bp) . q -------------
__global__ void k_wred(const float* __restrict__ T, const float* __restrict__ bp,
                       const float* __restrict__ q, float* __restrict__ wsum) {
    __shared__ float sb[6];
    if (threadIdx.x < 6) sb[threadIdx.x] = 0.f;
    __syncthreads();
    int gw = (blockIdx.x * blockDim.x + threadIdx.x) >> 5;
    int lane = threadIdx.x & 31;
    bool valid = gw < 2 * NN * 3;
    float s = 0.f;
    int t = 0, k = 0;
    if (valid) {
        t = gw / (NN * 3);
        int r = gw - t * NN * 3;
        k = r % 3;
        const float* tp = T + (size_t)gw * OUT_F;
        int j0 = lane * 4;
        float4 tv = *(const float4*)(tp + j0);
        float4 bv = *(const float4*)(bp + j0);
        float4 qv = *(const float4*)(q + j0);
        s = tanhf(tv.x + bv.x) * qv.x + tanhf(tv.y + bv.y) * qv.y
          + tanhf(tv.z + bv.z) * qv.z + tanhf(tv.w + bv.w) * qv.w;
    }
#pragma unroll
    for (int o = 16; o; o >>= 1) s += __shfl_down_sync(0xffffffffu, s, o);
    if (valid && lane == 0) atomicAdd(&sb[t * 3 + k], s);
    __syncthreads();
    if (threadIdx.x < 6 && sb[threadIdx.x] != 0.f) atomicAdd(&wsum[threadIdx.x], sb[threadIdx.x]);
}

__global__ void k_beta(const float* __restrict__ wsum, float* __restrict__ beta,
                       float* __restrict__ outBeta) {
    if (threadIdx.x != 0 || blockIdx.x != 0) return;
    for (int t = 0; t < 2; ++t) {
        float w0 = wsum[t * 3 + 0] / (float)NN;
        float w1 = wsum[t * 3 + 1] / (float)NN;
        float w2 = wsum[t * 3 + 2] / (float)NN;
        float m = fmaxf(w0, fmaxf(w1, w2));
        float e0 = expf(w0 - m), e1 = expf(w1 - m), e2 = expf(w2 - m);
        float inv = 1.f / (e0 + e1 + e2);
        beta[t * 3 + 0] = e0 * inv; outBeta[t * 3 + 0] = e0 * inv;
        beta[t * 3 + 1] = e1 * inv; outBeta[t * 3 + 1] = e1 * inv;
        beta[t * 3 + 2] = e2 * inv; outBeta[t * 3 + 2] = e2 * inv;
    }
}

__global__ void k_combine(const float* __restrict__ zd, const float* __restrict__ zp,
                          const float* __restrict__ beta, float* __restrict__ out) {
    int i = blockIdx.x * blockDim.x + threadIdx.x;
    if (i >= 2 * NN * OUT_F) return;
    int t = i / (NN * OUT_F);
    int r = i - t * NN * OUT_F;
    int n = r / OUT_F, f = r - n * OUT_F;
    const float* z = (t ? zp : zd) + (size_t)n * (3 * OUT_F) + f;
    const float* b = beta + t * 3;
    out[i] = b[0] * z[0] + b[1] * z[OUT_F] + b[2] * z[2 * OUT_F];
}

// ---------------- host orchestration ----------------
extern "C" void kernel_launch(void* const* d_in, const int* in_sizes, int n_in,
                              void* d_out, int out_size) {
    const float* xd  = (const float*)d_in[0];
    const float* xp  = (const float*)d_in[1];
    const int*   src = (const int*)  d_in[2];
    const int*   dst = (const int*)  d_in[3];
    const float* W1  = (const float*)d_in[4];
    const float* b1  = (const float*)d_in[5];
    const float* W2  = (const float*)d_in[6];
    const float* b2  = (const float*)d_in[7];
    const float* Wpm = (const float*)d_in[8];
    const float* bp  = (const float*)d_in[9];
    const float* q   = (const float*)d_in[10];
    float* out = (float*)d_out;

    float *y, *hd, *hp, *zd, *zp, *rout, *rin, *wsum, *beta;
    cudaGetSymbolAddress((void**)&y,    g_y);
    cudaGetSymbolAddress((void**)&hd,   g_hd);
    cudaGetSymbolAddress((void**)&hp,   g_hp);
    cudaGetSymbolAddress((void**)&zd,   g_zd);
    cudaGetSymbolAddress((void**)&zp,   g_zp);
    cudaGetSymbolAddress((void**)&rout, g_rout);
    cudaGetSymbolAddress((void**)&rin,  g_rin);
    cudaGetSymbolAddress((void**)&wsum, g_wsum);
    cudaGetSymbolAddress((void**)&beta, g_beta);

    const int T = 256;
    const int mblocks = (NN + BM - 1) / BM;   // 118

    // degrees for all (channel, relation) pairs
    k_zero<<<(16 * NN + T - 1) / T, T>>>(rout, 16 * NN);
    k_zero<<<(16 * NN + T - 1) / T, T>>>(rin, 16 * NN);
    k_count<<<(16 * EE + T - 1) / T, T>>>(src, dst, rout, rin);
    k_rsqrt<<<(16 * NN + T - 1) / T, T>>>(rout, 16 * NN);
    k_rsqrt<<<(16 * NN + T - 1) / T, T>>>(rin, 16 * NN);

    const int chans[3] = {0, 2, 3};

    for (int ci = 0; ci < 3; ++ci) {
        int c = chans[ci];

        // ---- layer 1: y_r = x_src @ W1[c][r], all 4 relations in one launch ----
        k_gemm_quad<IN_F, HID_F><<<dim3(4 * (HID_F / BN), mblocks), 256>>>(
            xd, xp, W1 + (size_t)c * 4 * IN_F * HID_F, y);

        k_bias2<<<(NN * HID_F + T - 1) / T, T>>>(hd, b1 + (c * 4 + 0) * HID_F,
                                                 b1 + (c * 4 + 2) * HID_F, HID_F, HID_F, 0);
        k_bias2<<<(NN * HID_F + T - 1) / T, T>>>(hp, b1 + (c * 4 + 1) * HID_F,
                                                 b1 + (c * 4 + 3) * HID_F, HID_F, HID_F, 0);
        for (int r = 0; r < 4; ++r) {
            int cr = c * 4 + r;
            float* accp = (r == 0 || r == 2) ? hd : hp;
            k_scatter<HID_F><<<EE / (256 / (HID_F / 4)), 256>>>(
                y + (size_t)r * NN * HID_F, src + (size_t)cr * EE, dst + (size_t)cr * EE,
                rout + cr * NN, rin + cr * NN, accp, HID_F, 0);
        }
        k_relu<<<(NN * HID_F + T - 1) / T, T>>>(hd, HID_F, HID_F, 0);
        k_relu<<<(NN * HID_F + T - 1) / T, T>>>(hp, HID_F, HID_F, 0);

        // ---- layer 2: y_r = h_src @ W2[c][r] ----
        k_gemm_quad<HID_F, OUT_F><<<dim3(4 * (OUT_F / BN), mblocks), 256>>>(
            hd, hp, W2 + (size_t)c * 4 * HID_F * OUT_F, y);

        k_bias2<<<(NN * OUT_F + T - 1) / T, T>>>(zd, b2 + (c * 4 + 0) * OUT_F,
                                                 b2 + (c * 4 + 2) * OUT_F, OUT_F, 3 * OUT_F, ci * OUT_F);
        k_bias2<<<(NN * OUT_F + T - 1) / T, T>>>(zp, b2 + (c * 4 + 1) * OUT_F,
                                                 b2 + (c * 4 + 3) * OUT_F, OUT_F, 3 * OUT_F, ci * OUT_F);
        for (int r = 0; r < 4; ++r) {
            int cr = c * 4 + r;
            float* accp = (r == 0 || r == 2) ? zd : zp;
            k_scatter<OUT_F><<<EE / (256 / (OUT_F / 4)), 256>>>(
                y + (size_t)r * NN * OUT_F, src + (size_t)cr * EE, dst + (size_t)cr * EE,
                rout + cr * NN, rin + cr * NN, accp, 3 * OUT_F, ci * OUT_F);
        }
        k_relu<<<(NN * OUT_F + T - 1) / T, T>>>(zd, OUT_F, 3 * OUT_F, ci * OUT_F);
        k_relu<<<(NN * OUT_F + T - 1) / T, T>>>(zp, OUT_F, 3 * OUT_F, ci * OUT_F);
    }

    // ---- semantic attention: T = Z @ Wp via GEMM into arena, then cheap reduction ----
    float* Tbuf = y;                                // arena is free now
    const int rowsPT = NN * 3;                      // 90000 rows per type
    const int amblocks = (rowsPT + BM - 1) / BM;    // 352
    k_gemm_one<<<dim3(OUT_F / BN, amblocks), 256>>>(zd, Wpm, Tbuf, rowsPT, OUT_F, OUT_F);
    k_gemm_one<<<dim3(OUT_F / BN, amblocks), 256>>>(zp, Wpm, Tbuf + (size_t)rowsPT * OUT_F,
                                                    rowsPT, OUT_F, OUT_F);
    k_zero<<<1, 32>>>(wsum, 8);
    int warps = 2 * NN * 3;
    k_wred<<<(warps * 32 + 255) / 256, 256>>>(Tbuf, bp, q, wsum);
    k_beta<<<1, 1>>>(wsum, beta, out + (size_t)2 * NN * OUT_F);
    k_combine<<<(2 * NN * OUT_F + T - 1) / T, T>>>(zd, zp, beta, out);
}

// round 4
// speedup vs baseline: 1.3689x; 1.2426x over previous
#include <cuda_runtime.h>
#include <cuda_bf16.h>
#include <cstdint>

#define NN 30000
#define EE 250000
#define IN_F 512
#define HID_F 256
#define OUT_F 128

typedef unsigned long long u64;
typedef __nv_bfloat16 bf16;

// ---------------- scratch (static device globals; no allocs) ----------------
__device__ float g_y[(size_t)4 * NN * HID_F];
__device__ float g_hd[(size_t)NN * HID_F];
__device__ float g_hp[(size_t)NN * HID_F];
__device__ float g_zd[(size_t)NN * 3 * OUT_F];
__device__ float g_zp[(size_t)NN * 3 * OUT_F];
__device__ float g_deg[32 * NN];
__device__ float g_wsum[8];
__device__ float g_beta[8];
// bf16 split operands (16B aligned for uint4 access)
__device__ __align__(16) bf16 g_xd1[(size_t)NN * IN_F];
__device__ __align__(16) bf16 g_xd2[(size_t)NN * IN_F];
__device__ __align__(16) bf16 g_xp1[(size_t)NN * IN_F];
__device__ __align__(16) bf16 g_xp2[(size_t)NN * IN_F];
__device__ __align__(16) bf16 g_hd1[(size_t)NN * HID_F];
__device__ __align__(16) bf16 g_hd2[(size_t)NN * HID_F];
__device__ __align__(16) bf16 g_hp1[(size_t)NN * HID_F];
__device__ __align__(16) bf16 g_hp2[(size_t)NN * HID_F];
__device__ __align__(16) bf16 g_wt1a[(size_t)12 * HID_F * IN_F];   // [12][N][K]
__device__ __align__(16) bf16 g_wt1b[(size_t)12 * HID_F * IN_F];
__device__ __align__(16) bf16 g_wt2a[(size_t)12 * OUT_F * HID_F];
__device__ __align__(16) bf16 g_wt2b[(size_t)12 * OUT_F * HID_F];
__device__ __align__(16) bf16 g_wpa[(size_t)OUT_F * OUT_F];        // Wp^T hi
__device__ __align__(16) bf16 g_wpb[(size_t)OUT_F * OUT_F];        // Wp^T lo

// ---------------- utility kernels ----------------
__global__ void k_zero(float* __restrict__ p, int n) {
    int i = blockIdx.x * blockDim.x + threadIdx.x;
    if (i < n) p[i] = 0.f;
}

__global__ void k_count(const int* __restrict__ s, const int* __restrict__ d,
                        float* __restrict__ deg) {
    int i = blockIdx.x * blockDim.x + threadIdx.x;
    if (i >= 16 * EE) return;
    int cr = i / EE;
    atomicAdd(&deg[cr * NN + s[i]], 1.f);
    atomicAdd(&deg[16 * NN + cr * NN + d[i]], 1.f);
}

__global__ void k_rsqrt(float* __restrict__ p, int n) {
    int i = blockIdx.x * blockDim.x + threadIdx.x;
    if (i < n) p[i] = rsqrtf(fmaxf(p[i], 1.f));
}

__global__ void k_bias2(float* __restrict__ acc, const float* __restrict__ ba,
                        const float* __restrict__ bb, int F, int stride, int colOff) {
    int i = blockIdx.x * blockDim.x + threadIdx.x;
    if (i >= NN * F) return;
    int n = i / F, f = i - n * F;
    acc[(size_t)n * stride + colOff + f] = ba[f] + bb[f];
}

__global__ void k_relu(float* __restrict__ p, int F, int stride, int colOff) {
    int i = blockIdx.x * blockDim.x + threadIdx.x;
    if (i >= NN * F) return;
    int n = i / F, f = i - n * F;
    size_t idx = (size_t)n * stride + colOff + f;
    p[idx] = fmaxf(p[idx], 0.f);
}

// split fp32 -> bf16 hi/lo
__global__ void k_split(const float* __restrict__ x, bf16* __restrict__ hi,
                        bf16* __restrict__ lo, int n4) {
    int i = blockIdx.x * blockDim.x + threadIdx.x;
    if (i >= n4) return;
    float4 v = ((const float4*)x)[i];
    bf16 h0 = __float2bfloat16(v.x), h1 = __float2bfloat16(v.y);
    bf16 h2 = __float2bfloat16(v.z), h3 = __float2bfloat16(v.w);
    ((__nv_bfloat162*)hi)[2 * i]     = __halves2bfloat162(h0, h1);
    ((__nv_bfloat162*)hi)[2 * i + 1] = __halves2bfloat162(h2, h3);
    bf16 l0 = __float2bfloat16(v.x - __bfloat162float(h0));
    bf16 l1 = __float2bfloat16(v.y - __bfloat162float(h1));
    bf16 l2 = __float2bfloat16(v.z - __bfloat162float(h2));
    bf16 l3 = __float2bfloat16(v.w - __bfloat162float(h3));
    ((__nv_bfloat162*)lo)[2 * i]     = __halves2bfloat162(l0, l1);
    ((__nv_bfloat162*)lo)[2 * i + 1] = __halves2bfloat162(l2, l3);
}

// transpose+split weights: W [16][K][N] fp32 (channels 0,2,3) -> [12][N][K] bf16 hi/lo
__global__ void k_wts(const float* __restrict__ W, bf16* __restrict__ t1,
                      bf16* __restrict__ t2, int K, int N) {
    __shared__ float tile[32][33];
    int z = blockIdx.z;
    int cz = z >> 2;
    int c = (cz == 0) ? 0 : (cz == 1 ? 2 : 3);
    const float* Wm = W + (size_t)(c * 4 + (z & 3)) * K * N;
    bf16* o1 = t1 + (size_t)z * K * N;
    bf16* o2 = t2 + (size_t)z * K * N;
    int k0 = blockIdx.y * 32, n0 = blockIdx.x * 32;
    for (int r = threadIdx.y; r < 32; r += 8)
        tile[r][threadIdx.x] = Wm[(size_t)(k0 + r) * N + n0 + threadIdx.x];
    __syncthreads();
    for (int r = threadIdx.y; r < 32; r += 8) {
        float v = tile[threadIdx.x][r];
        bf16 h = __float2bfloat16(v);
        size_t o = (size_t)(n0 + r) * K + k0 + threadIdx.x;
        o1[o] = h;
        o2[o] = __float2bfloat16(v - __bfloat162float(h));
    }
}

// single-matrix transpose+split
__global__ void k_wts1(const float* __restrict__ W, bf16* __restrict__ t1,
                       bf16* __restrict__ t2, int K, int N) {
    __shared__ float tile[32][33];
    int k0 = blockIdx.y * 32, n0 = blockIdx.x * 32;
    for (int r = threadIdx.y; r < 32; r += 8)
        tile[r][threadIdx.x] = W[(size_t)(k0 + r) * N + n0 + threadIdx.x];
    __syncthreads();
    for (int r = threadIdx.y; r < 32; r += 8) {
        float v = tile[threadIdx.x][r];
        bf16 h = __float2bfloat16(v);
        size_t o = (size_t)(n0 + r) * K + k0 + threadIdx.x;
        t1[o] = h;
        t2[o] = __float2bfloat16(v - __bfloat162float(h));
    }
}

// ---------------- mma.sync bf16 GEMM: Y[rel] = A_rel @ B_rel^T, 3-chain split ----------------
__device__ __forceinline__ void mma16816(float* c, const uint32_t* a, const uint32_t* b) {
    asm volatile("mma.sync.aligned.m16n8k16.row.col.f32.bf16.bf16.f32 "
                 "{%0,%1,%2,%3}, {%4,%5,%6,%7}, {%8,%9}, {%0,%1,%2,%3};"
                 : "+f"(c[0]), "+f"(c[1]), "+f"(c[2]), "+f"(c[3])
                 : "r"(a[0]), "r"(a[1]), "r"(a[2]), "r"(a[3]), "r"(b[0]), "r"(b[1]));
}

template <int KK, int NOUT>
__global__ void __launch_bounds__(256, 2) k_mma(
    const bf16* __restrict__ Ad1, const bf16* __restrict__ Ad2,
    const bf16* __restrict__ Ap1, const bf16* __restrict__ Ap2,
    const bf16* __restrict__ Bt1, const bf16* __restrict__ Bt2,
    float* __restrict__ Y, int M) {
    // smem in fragment word order; lane rotated by 8*(kb*2+h) for conflict-freedom
    __shared__ uint32_t AS[2][2048];   // 128 x 32 bf16
    __shared__ uint32_t BS[2][1024];   // 64 x 32 bf16

    const int tid = threadIdx.x;
    const int lane = tid & 31;
    const int wid = tid >> 5;
    const int warpM = wid & 3;
    const int warpN = wid >> 2;
    constexpr int NT = NOUT / 64;
    const int rel = blockIdx.x / NT;
    const int bn = (blockIdx.x % NT) * 64;
    const int bm = blockIdx.y * 128;

    const bf16* A1 = (rel < 2) ? Ad1 : Ap1;
    const bf16* A2 = (rel < 2) ? Ad2 : Ap2;
    const bf16* B1 = Bt1 + (size_t)rel * KK * NOUT;
    const bf16* B2 = Bt2 + (size_t)rel * KK * NOUT;
    float* Yp = Y + (size_t)rel * M * NOUT;

    const bf16* APass[3] = {A1, A1, A2};
    const bf16* BPass[3] = {B1, B2, B1};

    constexpr int CPP = KK / 32;
    constexpr int NC = 3 * CPP;

    float c[2][4][4];
#pragma unroll
    for (int i = 0; i < 2; ++i)
#pragma unroll
        for (int j = 0; j < 4; ++j)
#pragma unroll
            for (int l = 0; l < 4; ++l) c[i][j][l] = 0.f;

    uint4 va[2], vb;

    // prefetch chunk 0
    {
        const bf16* Ag = APass[0];
        const bf16* Bg = BPass[0];
#pragma unroll
        for (int i = 0; i < 2; ++i) {
            int u = tid + i * 256;
            int m = u >> 2, seg = u & 3;
            int gm = bm + m;
            va[i] = make_uint4(0, 0, 0, 0);
            if (gm < M)
                va[i] = *(const uint4*)(Ag + (size_t)gm * KK + (seg >> 1) * 16 + (seg & 1) * 8);
        }
        int n = tid >> 2, seg = tid & 3;
        vb = *(const uint4*)(Bg + (size_t)(bn + n) * KK + (seg >> 1) * 16 + (seg & 1) * 8);
    }

#pragma unroll 1
    for (int g = 0; g < NC; ++g) {
        const int buf = g & 1;
        // store prefetched chunk
#pragma unroll
        for (int i = 0; i < 2; ++i) {
            int u = tid + i * 256;
            int m = u >> 2, seg = u & 3;
            int kb = seg >> 1, h = seg & 1;
            int r = ((m >> 3) & 1) + 2 * h;
            int Lb = (((m & 7) * 4) + seg * 8) & 31;
            int W = ((kb * 8 + (m >> 4)) * 4 + r) * 32 + Lb;
            *(uint4*)&AS[buf][W] = va[i];
        }
        {
            int n = tid >> 2, seg = tid & 3;
            int kb = seg >> 1, h = seg & 1;
            int Lb = (((n & 7) * 4) + seg * 8) & 31;
            int W = ((kb * 8 + (n >> 3)) * 2 + h) * 32 + Lb;
            *(uint4*)&BS[buf][W] = vb;
        }
        __syncthreads();

        if (g + 1 < NC) {
            int pass = (g + 1) / CPP, kc = (g + 1) % CPP;
            const bf16* Ag = APass[pass];
            const bf16* Bg = BPass[pass];
            int koff = kc * 32;
#pragma unroll
            for (int i = 0; i < 2; ++i) {
                int u = tid + i * 256;
                int m = u >> 2, seg = u & 3;
                int gm = bm + m;
                va[i] = make_uint4(0, 0, 0, 0);
                if (gm < M)
                    va[i] = *(const uint4*)(Ag + (size_t)gm * KK + koff +
                                            (seg >> 1) * 16 + (seg & 1) * 8);
            }
            int n = tid >> 2, seg = tid & 3;
            vb = *(const uint4*)(Bg + (size_t)(bn + n) * KK + koff +
                                 (seg >> 1) * 16 + (seg & 1) * 8);
        }

        // compute
#pragma unroll
        for (int kb = 0; kb < 2; ++kb) {
            uint32_t a[2][4], b[4][2];
#pragma unroll
            for (int mbl = 0; mbl < 2; ++mbl) {
                int mb = warpM * 2 + mbl;
#pragma unroll
                for (int r = 0; r < 4; ++r) {
                    int Lr = (lane + (kb * 2 + (r >> 1)) * 8) & 31;
                    a[mbl][r] = AS[buf][((kb * 8 + mb) * 4 + r) * 32 + Lr];
                }
            }
#pragma unroll
            for (int nbl = 0; nbl < 4; ++nbl) {
                int nb = warpN * 4 + nbl;
#pragma unroll
                for (int h = 0; h < 2; ++h) {
                    int Lr = (lane + (kb * 2 + h) * 8) & 31;
                    b[nbl][h] = BS[buf][((kb * 8 + nb) * 2 + h) * 32 + Lr];
                }
            }
#pragma unroll
            for (int mbl = 0; mbl < 2; ++mbl)
#pragma unroll
                for (int nbl = 0; nbl < 4; ++nbl)
                    mma16816(c[mbl][nbl], a[mbl], b[nbl]);
        }
        __syncthreads();
    }

    // epilogue
#pragma unroll
    for (int mbl = 0; mbl < 2; ++mbl) {
        int mrow = bm + warpM * 32 + mbl * 16 + (lane >> 2);
#pragma unroll
        for (int nbl = 0; nbl < 4; ++nbl) {
            int ncol = bn + warpN * 32 + nbl * 8 + (lane & 3) * 2;
            float* base = Yp + (size_t)mrow * NOUT + ncol;
            if (mrow < M)
                *(float2*)base = make_float2(c[mbl][nbl][0], c[mbl][nbl][1]);
            if (mrow + 8 < M)
                *(float2*)(base + (size_t)8 * NOUT) = make_float2(c[mbl][nbl][2], c[mbl][nbl][3]);
        }
    }
}

// ------------- edge scatter: acc[d, colOff:+F] += rout[s]*rin[d] * y[s,:] -------------
template <int F>
__global__ void __launch_bounds__(256) k_scatter(const float* __restrict__ y,
                                                 const int* __restrict__ src,
                                                 const int* __restrict__ dst,
                                                 const float* __restrict__ rout,
                                                 const float* __restrict__ rin,
                                                 float* __restrict__ acc,
                                                 int stride, int colOff) {
    constexpr int TPE = F / 4;
    constexpr int EPB = 256 / TPE;
    int e = blockIdx.x * EPB + threadIdx.x / TPE;
    if (e >= EE) return;
    int l = threadIdx.x % TPE;
    int s = __ldg(&src[e]);
    int d = __ldg(&dst[e]);
    float coef = rout[s] * rin[d];
    float4 v = *(const float4*)(y + (size_t)s * F + l * 4);
    float* p = acc + (size_t)d * stride + colOff + l * 4;
    asm volatile("red.global.add.v4.f32 [%0], {%1, %2, %3, %4};"
                 :: "l"(p), "f"(v.x * coef), "f"(v.y * coef), "f"(v.z * coef), "f"(v.w * coef)
                 : "memory");
}

// ------------- attention tail -------------
__global__ void k_wred(const float* __restrict__ T, const float* __restrict__ bp,
                       const float* __restrict__ q, float* __restrict__ wsum) {
    __shared__ float sb[6];
    if (threadIdx.x < 6) sb[threadIdx.x] = 0.f;
    __syncthreads();
    int gw = (blockIdx.x * blockDim.x + threadIdx.x) >> 5;
    int lane = threadIdx.x & 31;
    bool valid = gw < 2 * NN * 3;
    float s = 0.f;
    int t = 0, k = 0;
    if (valid) {
        t = gw / (NN * 3);
        int r = gw - t * NN * 3;
        k = r % 3;
        const float* tp = T + (size_t)gw * OUT_F;
        int j0 = lane * 4;
        float4 tv = *(const float4*)(tp + j0);
        float4 bv = *(const float4*)(bp + j0);
        float4 qv = *(const float4*)(q + j0);
        s = tanhf(tv.x + bv.x) * qv.x + tanhf(tv.y + bv.y) * qv.y
          + tanhf(tv.z + bv.z) * qv.z + tanhf(tv.w + bv.w) * qv.w;
    }
#pragma unroll
    for (int o = 16; o; o >>= 1) s += __shfl_down_sync(0xffffffffu, s, o);
    if (valid && lane == 0) atomicAdd(&sb[t * 3 + k], s);
    __syncthreads();
    if (threadIdx.x < 6 && sb[threadIdx.x] != 0.f) atomicAdd(&wsum[threadIdx.x], sb[threadIdx.x]);
}

__global__ void k_beta(const float* __restrict__ wsum, float* __restrict__ beta,
                       float* __restrict__ outBeta) {
    if (threadIdx.x != 0 || blockIdx.x != 0) return;
    for (int t = 0; t < 2; ++t) {
        float w0 = wsum[t * 3 + 0] / (float)NN;
        float w1 = wsum[t * 3 + 1] / (float)NN;
        float w2 = wsum[t * 3 + 2] / (float)NN;
        float m = fmaxf(w0, fmaxf(w1, w2));
        float e0 = expf(w0 - m), e1 = expf(w1 - m), e2 = expf(w2 - m);
        float inv = 1.f / (e0 + e1 + e2);
        beta[t * 3 + 0] = e0 * inv; outBeta[t * 3 + 0] = e0 * inv;
        beta[t * 3 + 1] = e1 * inv; outBeta[t * 3 + 1] = e1 * inv;
        beta[t * 3 + 2] = e2 * inv; outBeta[t * 3 + 2] = e2 * inv;
    }
}

__global__ void k_combine(const float* __restrict__ zd, const float* __restrict__ zp,
                          const float* __restrict__ beta, float* __restrict__ out) {
    int i = blockIdx.x * blockDim.x + threadIdx.x;
    if (i >= 2 * NN * OUT_F) return;
    int t = i / (NN * OUT_F);
    int r = i - t * NN * OUT_F;
    int n = r / OUT_F, f = r - n * OUT_F;
    const float* z = (t ? zp : zd) + (size_t)n * (3 * OUT_F) + f;
    const float* b = beta + t * 3;
    out[i] = b[0] * z[0] + b[1] * z[OUT_F] + b[2] * z[2 * OUT_F];
}

// ---------------- host orchestration ----------------
extern "C" void kernel_launch(void* const* d_in, const int* in_sizes, int n_in,
                              void* d_out, int out_size) {
    const float* xd  = (const float*)d_in[0];
    const float* xp  = (const float*)d_in[1];
    const int*   src = (const int*)  d_in[2];
    const int*   dst = (const int*)  d_in[3];
    const float* W1  = (const float*)d_in[4];
    const float* b1  = (const float*)d_in[5];
    const float* W2  = (const float*)d_in[6];
    const float* b2  = (const float*)d_in[7];
    const float* Wpm = (const float*)d_in[8];
    const float* bp  = (const float*)d_in[9];
    const float* q   = (const float*)d_in[10];
    float* out = (float*)d_out;

    float *y, *hd, *hp, *zd, *zp, *deg, *wsum, *beta;
    bf16 *xd1, *xd2, *xp1, *xp2, *hd1, *hd2, *hp1, *hp2;
    bf16 *wt1a, *wt1b, *wt2a, *wt2b, *wpa, *wpb;
    cudaGetSymbolAddress((void**)&y,    g_y);
    cudaGetSymbolAddress((void**)&hd,   g_hd);
    cudaGetSymbolAddress((void**)&hp,   g_hp);
    cudaGetSymbolAddress((void**)&zd,   g_zd);
    cudaGetSymbolAddress((void**)&zp,   g_zp);
    cudaGetSymbolAddress((void**)&deg,  g_deg);
    cudaGetSymbolAddress((void**)&wsum, g_wsum);
    cudaGetSymbolAddress((void**)&beta, g_beta);
    cudaGetSymbolAddress((void**)&xd1,  g_xd1);
    cudaGetSymbolAddress((void**)&xd2,  g_xd2);
    cudaGetSymbolAddress((void**)&xp1,  g_xp1);
    cudaGetSymbolAddress((void**)&xp2,  g_xp2);
    cudaGetSymbolAddress((void**)&hd1,  g_hd1);
    cudaGetSymbolAddress((void**)&hd2,  g_hd2);
    cudaGetSymbolAddress((void**)&hp1,  g_hp1);
    cudaGetSymbolAddress((void**)&hp2,  g_hp2);
    cudaGetSymbolAddress((void**)&wt1a, g_wt1a);
    cudaGetSymbolAddress((void**)&wt1b, g_wt1b);
    cudaGetSymbolAddress((void**)&wt2a, g_wt2a);
    cudaGetSymbolAddress((void**)&wt2b, g_wt2b);
    cudaGetSymbolAddress((void**)&wpa,  g_wpa);
    cudaGetSymbolAddress((void**)&wpb,  g_wpb);

    const int T = 256;
    const int mtiles = (NN + 127) / 128;   // 235

    // weight transforms + input splits
    k_wts<<<dim3(HID_F / 32, IN_F / 32, 12), dim3(32, 8)>>>(W1, wt1a, wt1b, IN_F, HID_F);
    k_wts<<<dim3(OUT_F / 32, HID_F / 32, 12), dim3(32, 8)>>>(W2, wt2a, wt2b, HID_F, OUT_F);
    k_wts1<<<dim3(OUT_F / 32, OUT_F / 32), dim3(32, 8)>>>(Wpm, wpa, wpb, OUT_F, OUT_F);
    k_split<<<(NN * IN_F / 4 + T - 1) / T, T>>>(xd, xd1, xd2, NN * IN_F / 4);
    k_split<<<(NN * IN_F / 4 + T - 1) / T, T>>>(xp, xp1, xp2, NN * IN_F / 4);

    // degree tables
    k_zero<<<(32 * NN + T - 1) / T, T>>>(deg, 32 * NN);
    k_count<<<(16 * EE + T - 1) / T, T>>>(src, dst, deg);
    k_rsqrt<<<(32 * NN + T - 1) / T, T>>>(deg, 32 * NN);
    float* rout = deg;
    float* rin  = deg + 16 * NN;

    const int chans[3] = {0, 2, 3};

    for (int ci = 0; ci < 3; ++ci) {
        int c = chans[ci];

        // ---- layer 1: all 4 relations (tensor-core mma) ----
        k_mma<IN_F, HID_F><<<dim3(4 * (HID_F / 64), mtiles), 256>>>(
            xd1, xd2, xp1, xp2,
            wt1a + (size_t)ci * 4 * IN_F * HID_F, wt1b + (size_t)ci * 4 * IN_F * HID_F,
            y, NN);

        k_bias2<<<(NN * HID_F + T - 1) / T, T>>>(hd, b1 + (c * 4 + 0) * HID_F,
                                                 b1 + (c * 4 + 2) * HID_F, HID_F, HID_F, 0);
        k_bias2<<<(NN * HID_F + T - 1) / T, T>>>(hp, b1 + (c * 4 + 1) * HID_F,
                                                 b1 + (c * 4 + 3) * HID_F, HID_F, HID_F, 0);
        for (int r = 0; r < 4; ++r) {
            int cr = c * 4 + r;
            float* accp = (r == 0 || r == 2) ? hd : hp;
            k_scatter<HID_F><<<EE / (256 / (HID_F / 4)), 256>>>(
                y + (size_t)r * NN * HID_F, src + (size_t)cr * EE, dst + (size_t)cr * EE,
                rout + cr * NN, rin + cr * NN, accp, HID_F, 0);
        }
        k_relu<<<(NN * HID_F + T - 1) / T, T>>>(hd, HID_F, HID_F, 0);
        k_relu<<<(NN * HID_F + T - 1) / T, T>>>(hp, HID_F, HID_F, 0);

        k_split<<<(NN * HID_F / 4 + T - 1) / T, T>>>(hd, hd1, hd2, NN * HID_F / 4);
        k_split<<<(NN * HID_F / 4 + T - 1) / T, T>>>(hp, hp1, hp2, NN * HID_F / 4);

        // ---- layer 2 ----
        k_mma<HID_F, OUT_F><<<dim3(4 * (OUT_F / 64), mtiles), 256>>>(
            hd1, hd2, hp1, hp2,
            wt2a + (size_t)ci * 4 * HID_F * OUT_F, wt2b + (size_t)ci * 4 * HID_F * OUT_F,
            y, NN);

        k_bias2<<<(NN * OUT_F + T - 1) / T, T>>>(zd, b2 + (c * 4 + 0) * OUT_F,
                                                 b2 + (c * 4 + 2) * OUT_F, OUT_F, 3 * OUT_F, ci * OUT_F);
        k_bias2<<<(NN * OUT_F + T - 1) / T, T>>>(zp, b2 + (c * 4 + 1) * OUT_F,
                                                 b2 + (c * 4 + 3) * OUT_F, OUT_F, 3 * OUT_F, ci * OUT_F);
        for (int r = 0; r < 4; ++r) {
            int cr = c * 4 + r;
            float* accp = (r == 0 || r == 2) ? zd : zp;
            k_scatter<OUT_F><<<EE / (256 / (OUT_F / 4)), 256>>>(
                y + (size_t)r * NN * OUT_F, src + (size_t)cr * EE, dst + (size_t)cr * EE,
                rout + cr * NN, rin + cr * NN, accp, 3 * OUT_F, ci * OUT_F);
        }
        k_relu<<<(NN * OUT_F + T - 1) / T, T>>>(zd, OUT_F, 3 * OUT_F, ci * OUT_F);
        k_relu<<<(NN * OUT_F + T - 1) / T, T>>>(zp, OUT_F, 3 * OUT_F, ci * OUT_F);
    }

    // ---- semantic attention: split Z, T = Z @ Wp via mma, then reduction ----
    const int rowsPT = NN * 3;                      // 90000
    k_split<<<(rowsPT * OUT_F / 4 + T - 1) / T, T>>>(zd, xd1, xd2, rowsPT * OUT_F / 4);
    k_split<<<(rowsPT * OUT_F / 4 + T - 1) / T, T>>>(zp, xp1, xp2, rowsPT * OUT_F / 4);

    float* Tbuf = y;
    const int amtiles = (rowsPT + 127) / 128;       // 704
    k_mma<OUT_F, OUT_F><<<dim3(OUT_F / 64, amtiles), 256>>>(
        xd1, xd2, xd1, xd2, wpa, wpb, Tbuf, rowsPT);
    k_mma<OUT_F, OUT_F><<<dim3(OUT_F / 64, amtiles), 256>>>(
        xp1, xp2, xp1, xp2, wpa, wpb, Tbuf + (size_t)rowsPT * OUT_F, rowsPT);

    k_zero<<<1, 32>>>(wsum, 8);
    int warps = 2 * NN * 3;
    k_wred<<<(warps * 32 + 255) / 256, 256>>>(Tbuf, bp, q, wsum);
    k_beta<<<1, 1>>>(wsum, beta, out + (size_t)2 * NN * OUT_F);
    k_combine<<<(2 * NN * OUT_F + T - 1) / T, T>>>(zd, zp, beta, out);
}

// round 5
// speedup vs baseline: 1.8403x; 1.3444x over previous
#include <cuda_runtime.h>
#include <cuda_bf16.h>
#include <cstdint>

#define NN 30000
#define EE 250000
#define IN_F 512
#define HID_F 256
#define OUT_F 128

typedef unsigned long long u64;
typedef __nv_bfloat16 bf16;

// ---------------- scratch (static device globals; no allocs) ----------------
__device__ float g_y[(size_t)4 * NN * HID_F];
__device__ float g_zd[(size_t)NN * 3 * OUT_F];
__device__ float g_zp[(size_t)NN * 3 * OUT_F];
__device__ float g_deg[32 * NN];          // rout [0,16NN), rin [16NN,32NN)
__device__ float g_wsum[8];
__device__ float g_beta[8];
// CSR (12 used (channel,relation) pairs)
__device__ int   g_cnt[12 * NN];
__device__ int   g_base[12 * NN];
__device__ int   g_cur[12 * NN];
__device__ int   g_csrs[(size_t)12 * EE];
__device__ float g_csrw[(size_t)12 * EE];
// bf16 split operands
__device__ __align__(16) bf16 g_xd1[(size_t)NN * IN_F];
__device__ __align__(16) bf16 g_xd2[(size_t)NN * IN_F];
__device__ __align__(16) bf16 g_xp1[(size_t)NN * IN_F];
__device__ __align__(16) bf16 g_xp2[(size_t)NN * IN_F];
__device__ __align__(16) bf16 g_hd1[(size_t)NN * HID_F];
__device__ __align__(16) bf16 g_hd2[(size_t)NN * HID_F];
__device__ __align__(16) bf16 g_hp1[(size_t)NN * HID_F];
__device__ __align__(16) bf16 g_hp2[(size_t)NN * HID_F];
__device__ __align__(16) bf16 g_wt1a[(size_t)12 * HID_F * IN_F];
__device__ __align__(16) bf16 g_wt1b[(size_t)12 * HID_F * IN_F];
__device__ __align__(16) bf16 g_wt2a[(size_t)12 * OUT_F * HID_F];
__device__ __align__(16) bf16 g_wt2b[(size_t)12 * OUT_F * HID_F];
__device__ __align__(16) bf16 g_wpa[(size_t)OUT_F * OUT_F];
__device__ __align__(16) bf16 g_wpb[(size_t)OUT_F * OUT_F];

__device__ __forceinline__ void fma4(float4& a, float w, const float4 v) {
    a.x += w * v.x; a.y += w * v.y; a.z += w * v.z; a.w += w * v.w;
}

// map used-relation index u (0..11) -> cr (0..15)
__device__ __forceinline__ int u2cr(int u) {
    int ci = u >> 2;
    int c = (ci == 0) ? 0 : (ci == 1 ? 2 : 3);
    return c * 4 + (u & 3);
}

// ---------------- utility kernels ----------------
__global__ void k_zero(float* __restrict__ p, int n) {
    int i = blockIdx.x * blockDim.x + threadIdx.x;
    if (i < n) p[i] = 0.f;
}
__global__ void k_zeroi(int* __restrict__ p, int n) {
    int i = blockIdx.x * blockDim.x + threadIdx.x;
    if (i < n) p[i] = 0;
}

__global__ void k_count(const int* __restrict__ s, const int* __restrict__ d,
                        float* __restrict__ deg) {
    int i = blockIdx.x * blockDim.x + threadIdx.x;
    if (i >= 16 * EE) return;
    int cr = i / EE;
    atomicAdd(&deg[cr * NN + s[i]], 1.f);
    atomicAdd(&deg[16 * NN + cr * NN + d[i]], 1.f);
}

__global__ void k_rsqrt(float* __restrict__ p, int n) {
    int i = blockIdx.x * blockDim.x + threadIdx.x;
    if (i < n) p[i] = rsqrtf(fmaxf(p[i], 1.f));
}

__global__ void k_hist(const int* __restrict__ dst, int* __restrict__ cnt) {
    int i = blockIdx.x * blockDim.x + threadIdx.x;
    if (i >= 12 * EE) return;
    int u = i / EE, e = i - u * EE;
    atomicAdd(&cnt[u * NN + dst[(size_t)u2cr(u) * EE + e]], 1);
}

// deterministic exclusive scan per u (12 blocks, 1024 threads)
__global__ void k_scan(const int* __restrict__ cnt, int* __restrict__ base,
                       int* __restrict__ cur) {
    __shared__ int ws[32];
    __shared__ int carry;
    int u = blockIdx.x;
    const int* c = cnt + u * NN;
    int* b = base + u * NN;
    int* q = cur + u * NN;
    int lane = threadIdx.x & 31, w = threadIdx.x >> 5;
    if (threadIdx.x == 0) carry = 0;
    __syncthreads();
    for (int off = 0; off < NN; off += 1024) {
        int i = off + threadIdx.x;
        int v = (i < NN) ? c[i] : 0;
        int s = v;
#pragma unroll
        for (int o = 1; o < 32; o <<= 1) {
            int t = __shfl_up_sync(0xffffffffu, s, o);
            if (lane >= o) s += t;
        }
        if (lane == 31) ws[w] = s;
        __syncthreads();
        if (w == 0) {
            int t2 = ws[lane];
#pragma unroll
            for (int o = 1; o < 32; o <<= 1) {
                int t = __shfl_up_sync(0xffffffffu, t2, o);
                if (lane >= o) t2 += t;
            }
            ws[lane] = t2;
        }
        __syncthreads();
        int excl = s - v + (w > 0 ? ws[w - 1] : 0) + carry;
        if (i < NN) { b[i] = excl; q[i] = excl; }
        __syncthreads();
        if (threadIdx.x == 1023) carry = excl + v;
        __syncthreads();
    }
}

__global__ void k_fill(const int* __restrict__ src, const int* __restrict__ dst,
                       const float* __restrict__ rout, int* __restrict__ cur,
                       int* __restrict__ csrs, float* __restrict__ csrw) {
    int i = blockIdx.x * blockDim.x + threadIdx.x;
    if (i >= 12 * EE) return;
    int u = i / EE, e = i - u * EE;
    int cr = u2cr(u);
    int s = src[(size_t)cr * EE + e];
    int d = dst[(size_t)cr * EE + e];
    int pos = atomicAdd(&cur[u * NN + d], 1);
    csrs[(size_t)u * EE + pos] = s;
    csrw[(size_t)u * EE + pos] = rout[cr * NN + s];
}

// split fp32 -> bf16 hi/lo
__global__ void k_split(const float* __restrict__ x, bf16* __restrict__ hi,
                        bf16* __restrict__ lo, int n4) {
    int i = blockIdx.x * blockDim.x + threadIdx.x;
    if (i >= n4) return;
    float4 v = ((const float4*)x)[i];
    bf16 h0 = __float2bfloat16(v.x), h1 = __float2bfloat16(v.y);
    bf16 h2 = __float2bfloat16(v.z), h3 = __float2bfloat16(v.w);
    ((__nv_bfloat162*)hi)[2 * i]     = __halves2bfloat162(h0, h1);
    ((__nv_bfloat162*)hi)[2 * i + 1] = __halves2bfloat162(h2, h3);
    bf16 l0 = __float2bfloat16(v.x - __bfloat162float(h0));
    bf16 l1 = __float2bfloat16(v.y - __bfloat162float(h1));
    bf16 l2 = __float2bfloat16(v.z - __bfloat162float(h2));
    bf16 l3 = __float2bfloat16(v.w - __bfloat162float(h3));
    ((__nv_bfloat162*)lo)[2 * i]     = __halves2bfloat162(l0, l1);
    ((__nv_bfloat162*)lo)[2 * i + 1] = __halves2bfloat162(l2, l3);
}

// transpose+split weights: W [16][K][N] fp32 (channels 0,2,3) -> [12][N][K] bf16 hi/lo
__global__ void k_wts(const float* __restrict__ W, bf16* __restrict__ t1,
                      bf16* __restrict__ t2, int K, int N) {
    __shared__ float tile[32][33];
    int z = blockIdx.z;
    int cz = z >> 2;
    int c = (cz == 0) ? 0 : (cz == 1 ? 2 : 3);
    const float* Wm = W + (size_t)(c * 4 + (z & 3)) * K * N;
    bf16* o1 = t1 + (size_t)z * K * N;
    bf16* o2 = t2 + (size_t)z * K * N;
    int k0 = blockIdx.y * 32, n0 = blockIdx.x * 32;
    for (int r = threadIdx.y; r < 32; r += 8)
        tile[r][threadIdx.x] = Wm[(size_t)(k0 + r) * N + n0 + threadIdx.x];
    __syncthreads();
    for (int r = threadIdx.y; r < 32; r += 8) {
        float v = tile[threadIdx.x][r];
        bf16 h = __float2bfloat16(v);
        size_t o = (size_t)(n0 + r) * K + k0 + threadIdx.x;
        o1[o] = h;
        o2[o] = __float2bfloat16(v - __bfloat162float(h));
    }
}

__global__ void k_wts1(const float* __restrict__ W, bf16* __restrict__ t1,
                       bf16* __restrict__ t2, int K, int N) {
    __shared__ float tile[32][33];
    int k0 = blockIdx.y * 32, n0 = blockIdx.x * 32;
    for (int r = threadIdx.y; r < 32; r += 8)
        tile[r][threadIdx.x] = W[(size_t)(k0 + r) * N + n0 + threadIdx.x];
    __syncthreads();
    for (int r = threadIdx.y; r < 32; r += 8) {
        float v = tile[threadIdx.x][r];
        bf16 h = __float2bfloat16(v);
        size_t o = (size_t)(n0 + r) * K + k0 + threadIdx.x;
        t1[o] = h;
        t2[o] = __float2bfloat16(v - __bfloat162float(h));
    }
}

// ---------------- mma.sync bf16 GEMM (unchanged from R4) ----------------
__device__ __forceinline__ void mma16816(float* c, const uint32_t* a, const uint32_t* b) {
    asm volatile("mma.sync.aligned.m16n8k16.row.col.f32.bf16.bf16.f32 "
                 "{%0,%1,%2,%3}, {%4,%5,%6,%7}, {%8,%9}, {%0,%1,%2,%3};"
                 : "+f"(c[0]), "+f"(c[1]), "+f"(c[2]), "+f"(c[3])
                 : "r"(a[0]), "r"(a[1]), "r"(a[2]), "r"(a[3]), "r"(b[0]), "r"(b[1]));
}

template <int KK, int NOUT>
__global__ void __launch_bounds__(256, 2) k_mma(
    const bf16* __restrict__ Ad1, const bf16* __restrict__ Ad2,
    const bf16* __restrict__ Ap1, const bf16* __restrict__ Ap2,
    const bf16* __restrict__ Bt1, const bf16* __restrict__ Bt2,
    float* __restrict__ Y, int M) {
    __shared__ uint32_t AS[2][2048];
    __shared__ uint32_t BS[2][1024];

    const int tid = threadIdx.x;
    const int lane = tid & 31;
    const int wid = tid >> 5;
    const int warpM = wid & 3;
    const int warpN = wid >> 2;
    constexpr int NT = NOUT / 64;
    const int rel = blockIdx.x / NT;
    const int bn = (blockIdx.x % NT) * 64;
    const int bm = blockIdx.y * 128;

    const bf16* A1 = (rel < 2) ? Ad1 : Ap1;
    const bf16* A2 = (rel < 2) ? Ad2 : Ap2;
    const bf16* B1 = Bt1 + (size_t)rel * KK * NOUT;
    const bf16* B2 = Bt2 + (size_t)rel * KK * NOUT;
    float* Yp = Y + (size_t)rel * M * NOUT;

    const bf16* APass[3] = {A1, A1, A2};
    const bf16* BPass[3] = {B1, B2, B1};

    constexpr int CPP = KK / 32;
    constexpr int NC = 3 * CPP;

    float c[2][4][4];
#pragma unroll
    for (int i = 0; i < 2; ++i)
#pragma unroll
        for (int j = 0; j < 4; ++j)
#pragma unroll
            for (int l = 0; l < 4; ++l) c[i][j][l] = 0.f;

    uint4 va[2], vb;
    {
        const bf16* Ag = APass[0];
        const bf16* Bg = BPass[0];
#pragma unroll
        for (int i = 0; i < 2; ++i) {
            int u = tid + i * 256;
            int m = u >> 2, seg = u & 3;
            int gm = bm + m;
            va[i] = make_uint4(0, 0, 0, 0);
            if (gm < M)
                va[i] = *(const uint4*)(Ag + (size_t)gm * KK + (seg >> 1) * 16 + (seg & 1) * 8);
        }
        int n = tid >> 2, seg = tid & 3;
        vb = *(const uint4*)(Bg + (size_t)(bn + n) * KK + (seg >> 1) * 16 + (seg & 1) * 8);
    }

#pragma unroll 1
    for (int g = 0; g < NC; ++g) {
        const int buf = g & 1;
#pragma unroll
        for (int i = 0; i < 2; ++i) {
            int u = tid + i * 256;
            int m = u >> 2, seg = u & 3;
            int kb = seg >> 1, h = seg & 1;
            int r = ((m >> 3) & 1) + 2 * h;
            int Lb = (((m & 7) * 4) + seg * 8) & 31;
            int W = ((kb * 8 + (m >> 4)) * 4 + r) * 32 + Lb;
            *(uint4*)&AS[buf][W] = va[i];
        }
        {
            int n = tid >> 2, seg = tid & 3;
            int kb = seg >> 1, h = seg & 1;
            int Lb = (((n & 7) * 4) + seg * 8) & 31;
            int W = ((kb * 8 + (n >> 3)) * 2 + h) * 32 + Lb;
            *(uint4*)&BS[buf][W] = vb;
        }
        __syncthreads();

        if (g + 1 < NC) {
            int pass = (g + 1) / CPP, kc = (g + 1) % CPP;
            const bf16* Ag = APass[pass];
            const bf16* Bg = BPass[pass];
            int koff = kc * 32;
#pragma unroll
            for (int i = 0; i < 2; ++i) {
                int u = tid + i * 256;
                int m = u >> 2, seg = u & 3;
                int gm = bm + m;
                va[i] = make_uint4(0, 0, 0, 0);
                if (gm < M)
                    va[i] = *(const uint4*)(Ag + (size_t)gm * KK + koff +
                                            (seg >> 1) * 16 + (seg & 1) * 8);
            }
            int n = tid >> 2, seg = tid & 3;
            vb = *(const uint4*)(Bg + (size_t)(bn + n) * KK + koff +
                                 (seg >> 1) * 16 + (seg & 1) * 8);
        }

#pragma unroll
        for (int kb = 0; kb < 2; ++kb) {
            uint32_t a[2][4], b[4][2];
#pragma unroll
            for (int mbl = 0; mbl < 2; ++mbl) {
                int mb = warpM * 2 + mbl;
#pragma unroll
                for (int r = 0; r < 4; ++r) {
                    int Lr = (lane + (kb * 2 + (r >> 1)) * 8) & 31;
                    a[mbl][r] = AS[buf][((kb * 8 + mb) * 4 + r) * 32 + Lr];
                }
            }
#pragma unroll
            for (int nbl = 0; nbl < 4; ++nbl) {
                int nb = warpN * 4 + nbl;
#pragma unroll
                for (int h = 0; h < 2; ++h) {
                    int Lr = (lane + (kb * 2 + h) * 8) & 31;
                    b[nbl][h] = BS[buf][((kb * 8 + nb) * 2 + h) * 32 + Lr];
                }
            }
#pragma unroll
            for (int mbl = 0; mbl < 2; ++mbl)
#pragma unroll
                for (int nbl = 0; nbl < 4; ++nbl)
                    mma16816(c[mbl][nbl], a[mbl], b[nbl]);
        }
        __syncthreads();
    }

#pragma unroll
    for (int mbl = 0; mbl < 2; ++mbl) {
        int mrow = bm + warpM * 32 + mbl * 16 + (lane >> 2);
#pragma unroll
        for (int nbl = 0; nbl < 4; ++nbl) {
            int ncol = bn + warpN * 32 + nbl * 8 + (lane & 3) * 2;
            float* base = Yp + (size_t)mrow * NOUT + ncol;
            if (mrow < M)
                *(float2*)base = make_float2(c[mbl][nbl][0], c[mbl][nbl][1]);
            if (mrow + 8 < M)
                *(float2*)(base + (size_t)8 * NOUT) = make_float2(c[mbl][nbl][2], c[mbl][nbl][3]);
        }
    }
}

// --------- fused gather layer1: hd = relu(bLo+bHi + rinLo*Σw*yLo + rinHi*Σw*yHi), split ---------
__global__ void __launch_bounds__(256) k_gag1(
    const float* __restrict__ yLo, const float* __restrict__ yHi,
    const int* __restrict__ csLo, const float* __restrict__ cwLo,
    const int* __restrict__ bsLo, const int* __restrict__ ctLo,
    const int* __restrict__ csHi, const float* __restrict__ cwHi,
    const int* __restrict__ bsHi, const int* __restrict__ ctHi,
    const float* __restrict__ rinLo, const float* __restrict__ rinHi,
    const float* __restrict__ bLo, const float* __restrict__ bHi,
    bf16* __restrict__ o1, bf16* __restrict__ o2) {
    int gw = (blockIdx.x * blockDim.x + threadIdx.x) >> 5;
    if (gw >= NN) return;
    int lane = threadIdx.x & 31;
    int d = gw;
    float4 a0 = make_float4(0, 0, 0, 0), a1 = a0, c0 = a0, c1 = a0;
    {
        int b = bsLo[d], n = ctLo[d];
        for (int i = 0; i < n; ++i) {
            int s = csLo[b + i];
            float w = cwLo[b + i];
            const float4* r = (const float4*)(yLo + (size_t)s * HID_F);
            fma4(a0, w, r[lane]);
            fma4(a1, w, r[32 + lane]);
        }
    }
    {
        int b = bsHi[d], n = ctHi[d];
        for (int i = 0; i < n; ++i) {
            int s = csHi[b + i];
            float w = cwHi[b + i];
            const float4* r = (const float4*)(yHi + (size_t)s * HID_F);
            fma4(c0, w, r[lane]);
            fma4(c1, w, r[32 + lane]);
        }
    }
    float rl = rinLo[d], rh = rinHi[d];
    float4 bb0, bb1;
    {
        float4 x = ((const float4*)bLo)[lane], y = ((const float4*)bHi)[lane];
        bb0 = make_float4(x.x + y.x, x.y + y.y, x.z + y.z, x.w + y.w);
        x = ((const float4*)bLo)[32 + lane]; y = ((const float4*)bHi)[32 + lane];
        bb1 = make_float4(x.x + y.x, x.y + y.y, x.z + y.z, x.w + y.w);
    }
#pragma unroll
    for (int ch = 0; ch < 2; ++ch) {
        float4 A = ch ? a1 : a0, C = ch ? c1 : c0, B = ch ? bb1 : bb0;
        float r0 = fmaxf(B.x + rl * A.x + rh * C.x, 0.f);
        float r1 = fmaxf(B.y + rl * A.y + rh * C.y, 0.f);
        float r2 = fmaxf(B.z + rl * A.z + rh * C.z, 0.f);
        float r3 = fmaxf(B.w + rl * A.w + rh * C.w, 0.f);
        bf16 h0 = __float2bfloat16(r0), h1 = __float2bfloat16(r1);
        bf16 h2 = __float2bfloat16(r2), h3 = __float2bfloat16(r3);
        __nv_bfloat162 p0 = __halves2bfloat162(h0, h1);
        __nv_bfloat162 p1 = __halves2bfloat162(h2, h3);
        uint2 st;
        st.x = *(unsigned*)&p0; st.y = *(unsigned*)&p1;
        size_t off = (size_t)d * HID_F + ch * 128 + lane * 4;
        *(uint2*)(o1 + off) = st;
        bf16 l0 = __float2bfloat16(r0 - __bfloat162float(h0));
        bf16 l1 = __float2bfloat16(r1 - __bfloat162float(h1));
        bf16 l2 = __float2bfloat16(r2 - __bfloat162float(h2));
        bf16 l3 = __float2bfloat16(r3 - __bfloat162float(h3));
        p0 = __halves2bfloat162(l0, l1);
        p1 = __halves2bfloat162(l2, l3);
        st.x = *(unsigned*)&p0; st.y = *(unsigned*)&p1;
        *(uint2*)(o2 + off) = st;
    }
}

// --------- fused gather layer2: z[:, colOff:+128] = relu(b + rinLo*Σ + rinHi*Σ) ---------
__global__ void __launch_bounds__(256) k_gag2(
    const float* __restrict__ yLo, const float* __restrict__ yHi,
    const int* __restrict__ csLo, const float* __restrict__ cwLo,
    const int* __restrict__ bsLo, const int* __restrict__ ctLo,
    const int* __restrict__ csHi, const float* __restrict__ cwHi,
    const int* __restrict__ bsHi, const int* __restrict__ ctHi,
    const float* __restrict__ rinLo, const float* __restrict__ rinHi,
    const float* __restrict__ bLo, const float* __restrict__ bHi,
    float* __restrict__ outz, int colOff) {
    int gw = (blockIdx.x * blockDim.x + threadIdx.x) >> 5;
    if (gw >= NN) return;
    int lane = threadIdx.x & 31;
    int d = gw;
    float4 a0 = make_float4(0, 0, 0, 0), c0 = a0;
    {
        int b = bsLo[d], n = ctLo[d];
        for (int i = 0; i < n; ++i) {
            int s = csLo[b + i];
            float w = cwLo[b + i];
            fma4(a0, w, ((const float4*)(yLo + (size_t)s * OUT_F))[lane]);
        }
    }
    {
        int b = bsHi[d], n = ctHi[d];
        for (int i = 0; i < n; ++i) {
            int s = csHi[b + i];
            float w = cwHi[b + i];
            fma4(c0, w, ((const float4*)(yHi + (size_t)s * OUT_F))[lane]);
        }
    }
    float rl = rinLo[d], rh = rinHi[d];
    float4 x = ((const float4*)bLo)[lane], y = ((const float4*)bHi)[lane];
    float4 res;
    res.x = fmaxf(x.x + y.x + rl * a0.x + rh * c0.x, 0.f);
    res.y = fmaxf(x.y + y.y + rl * a0.y + rh * c0.y, 0.f);
    res.z = fmaxf(x.z + y.z + rl * a0.z + rh * c0.z, 0.f);
    res.w = fmaxf(x.w + y.w + rl * a0.w + rh * c0.w, 0.f);
    *(float4*)(outz + (size_t)d * (3 * OUT_F) + colOff + lane * 4) = res;
}

// ------------- attention tail -------------
__global__ void k_wred(const float* __restrict__ T, const float* __restrict__ bp,
                       const float* __restrict__ q, float* __restrict__ wsum) {
    __shared__ float sb[6];
    if (threadIdx.x < 6) sb[threadIdx.x] = 0.f;
    __syncthreads();
    int gw = (blockIdx.x * blockDim.x + threadIdx.x) >> 5;
    int lane = threadIdx.x & 31;
    bool valid = gw < 2 * NN * 3;
    float s = 0.f;
    int t = 0, k = 0;
    if (valid) {
        t = gw / (NN * 3);
        int r = gw - t * NN * 3;
        k = r % 3;
        const float* tp = T + (size_t)gw * OUT_F;
        int j0 = lane * 4;
        float4 tv = *(const float4*)(tp + j0);
        float4 bv = *(const float4*)(bp + j0);
        float4 qv = *(const float4*)(q + j0);
        s = tanhf(tv.x + bv.x) * qv.x + tanhf(tv.y + bv.y) * qv.y
          + tanhf(tv.z + bv.z) * qv.z + tanhf(tv.w + bv.w) * qv.w;
    }
#pragma unroll
    for (int o = 16; o; o >>= 1) s += __shfl_down_sync(0xffffffffu, s, o);
    if (valid && lane == 0) atomicAdd(&sb[t * 3 + k], s);
    __syncthreads();
    if (threadIdx.x < 6 && sb[threadIdx.x] != 0.f) atomicAdd(&wsum[threadIdx.x], sb[threadIdx.x]);
}

__global__ void k_beta(const float* __restrict__ wsum, float* __restrict__ beta,
                       float* __restrict__ outBeta) {
    if (threadIdx.x != 0 || blockIdx.x != 0) return;
    for (int t = 0; t < 2; ++t) {
        float w0 = wsum[t * 3 + 0] / (float)NN;
        float w1 = wsum[t * 3 + 1] / (float)NN;
        float w2 = wsum[t * 3 + 2] / (float)NN;
        float m = fmaxf(w0, fmaxf(w1, w2));
        float e0 = expf(w0 - m), e1 = expf(w1 - m), e2 = expf(w2 - m);
        float inv = 1.f / (e0 + e1 + e2);
        beta[t * 3 + 0] = e0 * inv; outBeta[t * 3 + 0] = e0 * inv;
        beta[t * 3 + 1] = e1 * inv; outBeta[t * 3 + 1] = e1 * inv;
        beta[t * 3 + 2] = e2 * inv; outBeta[t * 3 + 2] = e2 * inv;
    }
}

__global__ void k_combine(const float* __restrict__ zd, const float* __restrict__ zp,
                          const float* __restrict__ beta, float* __restrict__ out) {
    int i = blockIdx.x * blockDim.x + threadIdx.x;
    if (i >= 2 * NN * OUT_F) return;
    int t = i / (NN * OUT_F);
    int r = i - t * NN * OUT_F;
    int n = r / OUT_F, f = r - n * OUT_F;
    const float* z = (t ? zp : zd) + (size_t)n * (3 * OUT_F) + f;
    const float* b = beta + t * 3;
    out[i] = b[0] * z[0] + b[1] * z[OUT_F] + b[2] * z[2 * OUT_F];
}

// ---------------- host orchestration ----------------
extern "C" void kernel_launch(void* const* d_in, const int* in_sizes, int n_in,
                              void* d_out, int out_size) {
    const float* xd  = (const float*)d_in[0];
    const float* xp  = (const float*)d_in[1];
    const int*   src = (const int*)  d_in[2];
    const int*   dst = (const int*)  d_in[3];
    const float* W1  = (const float*)d_in[4];
    const float* b1  = (const float*)d_in[5];
    const float* W2  = (const float*)d_in[6];
    const float* b2  = (const float*)d_in[7];
    const float* Wpm = (const float*)d_in[8];
    const float* bp  = (const float*)d_in[9];
    const float* q   = (const float*)d_in[10];
    float* out = (float*)d_out;

    float *y, *zd, *zp, *deg, *wsum, *beta;
    int *cnt, *base, *cur, *csrs;
    float *csrw;
    bf16 *xd1, *xd2, *xp1, *xp2, *hd1, *hd2, *hp1, *hp2;
    bf16 *wt1a, *wt1b, *wt2a, *wt2b, *wpa, *wpb;
    cudaGetSymbolAddress((void**)&y,    g_y);
    cudaGetSymbolAddress((void**)&zd,   g_zd);
    cudaGetSymbolAddress((void**)&zp,   g_zp);
    cudaGetSymbolAddress((void**)&deg,  g_deg);
    cudaGetSymbolAddress((void**)&wsum, g_wsum);
    cudaGetSymbolAddress((void**)&beta, g_beta);
    cudaGetSymbolAddress((void**)&cnt,  g_cnt);
    cudaGetSymbolAddress((void**)&base, g_base);
    cudaGetSymbolAddress((void**)&cur,  g_cur);
    cudaGetSymbolAddress((void**)&csrs, g_csrs);
    cudaGetSymbolAddress((void**)&csrw, g_csrw);
    cudaGetSymbolAddress((void**)&xd1,  g_xd1);
    cudaGetSymbolAddress((void**)&xd2,  g_xd2);
    cudaGetSymbolAddress((void**)&xp1,  g_xp1);
    cudaGetSymbolAddress((void**)&xp2,  g_xp2);
    cudaGetSymbolAddress((void**)&hd1,  g_hd1);
    cudaGetSymbolAddress((void**)&hd2,  g_hd2);
    cudaGetSymbolAddress((void**)&hp1,  g_hp1);
    cudaGetSymbolAddress((void**)&hp2,  g_hp2);
    cudaGetSymbolAddress((void**)&wt1a, g_wt1a);
    cudaGetSymbolAddress((void**)&wt1b, g_wt1b);
    cudaGetSymbolAddress((void**)&wt2a, g_wt2a);
    cudaGetSymbolAddress((void**)&wt2b, g_wt2b);
    cudaGetSymbolAddress((void**)&wpa,  g_wpa);
    cudaGetSymbolAddress((void**)&wpb,  g_wpb);

    const int T = 256;
    const int mtiles = (NN + 127) / 128;

    // degrees + CSR
    k_zero<<<(32 * NN + T - 1) / T, T>>>(deg, 32 * NN);
    k_count<<<(16 * EE + T - 1) / T, T>>>(src, dst, deg);
    k_rsqrt<<<(32 * NN + T - 1) / T, T>>>(deg, 32 * NN);
    k_zeroi<<<(12 * NN + T - 1) / T, T>>>(cnt, 12 * NN);
    k_hist<<<(12 * EE + T - 1) / T, T>>>(dst, cnt);
    k_scan<<<12, 1024>>>(cnt, base, cur);
    k_fill<<<(12 * EE + T - 1) / T, T>>>(src, dst, deg, cur, csrs, csrw);
    float* rin = deg + 16 * NN;

    // weight transforms + input splits
    k_wts<<<dim3(HID_F / 32, IN_F / 32, 12), dim3(32, 8)>>>(W1, wt1a, wt1b, IN_F, HID_F);
    k_wts<<<dim3(OUT_F / 32, HID_F / 32, 12), dim3(32, 8)>>>(W2, wt2a, wt2b, HID_F, OUT_F);
    k_wts1<<<dim3(OUT_F / 32, OUT_F / 32), dim3(32, 8)>>>(Wpm, wpa, wpb, OUT_F, OUT_F);
    k_split<<<(NN * IN_F / 4 + T - 1) / T, T>>>(xd, xd1, xd2, NN * IN_F / 4);
    k_split<<<(NN * IN_F / 4 + T - 1) / T, T>>>(xp, xp1, xp2, NN * IN_F / 4);

    const int chans[3] = {0, 2, 3};
    const int gblocks = (NN * 32 + T - 1) / T;   // one warp per node

    for (int ci = 0; ci < 3; ++ci) {
        int c = chans[ci];
        int u0 = ci * 4;

        // ---- layer 1 GEMMs ----
        k_mma<IN_F, HID_F><<<dim3(4 * (HID_F / 64), mtiles), 256>>>(
            xd1, xd2, xp1, xp2,
            wt1a + (size_t)ci * 4 * IN_F * HID_F, wt1b + (size_t)ci * 4 * IN_F * HID_F,
            y, NN);

        // ---- fused gather+bias+relu+split: drug (rel 0 & 2), protein (rel 1 & 3) ----
        k_gag1<<<gblocks, T>>>(
            y + (size_t)0 * NN * HID_F, y + (size_t)2 * NN * HID_F,
            csrs + (size_t)(u0 + 0) * EE, csrw + (size_t)(u0 + 0) * EE,
            base + (u0 + 0) * NN, cnt + (u0 + 0) * NN,
            csrs + (size_t)(u0 + 2) * EE, csrw + (size_t)(u0 + 2) * EE,
            base + (u0 + 2) * NN, cnt + (u0 + 2) * NN,
            rin + (c * 4 + 0) * NN, rin + (c * 4 + 2) * NN,
            b1 + (c * 4 + 0) * HID_F, b1 + (c * 4 + 2) * HID_F,
            hd1, hd2);
        k_gag1<<<gblocks, T>>>(
            y + (size_t)1 * NN * HID_F, y + (size_t)3 * NN * HID_F,
            csrs + (size_t)(u0 + 1) * EE, csrw + (size_t)(u0 + 1) * EE,
            base + (u0 + 1) * NN, cnt + (u0 + 1) * NN,
            csrs + (size_t)(u0 + 3) * EE, csrw + (size_t)(u0 + 3) * EE,
            base + (u0 + 3) * NN, cnt + (u0 + 3) * NN,
            rin + (c * 4 + 1) * NN, rin + (c * 4 + 3) * NN,
            b1 + (c * 4 + 1) * HID_F, b1 + (c * 4 + 3) * HID_F,
            hp1, hp2);

        // ---- layer 2 GEMMs ----
        k_mma<HID_F, OUT_F><<<dim3(4 * (OUT_F / 64), mtiles), 256>>>(
            hd1, hd2, hp1, hp2,
            wt2a + (size_t)ci * 4 * HID_F * OUT_F, wt2b + (size_t)ci * 4 * HID_F * OUT_F,
            y, NN);

        k_gag2<<<gblocks, T>>>(
            y + (size_t)0 * NN * OUT_F, y + (size_t)2 * NN * OUT_F,
            csrs + (size_t)(u0 + 0) * EE, csrw + (size_t)(u0 + 0) * EE,
            base + (u0 + 0) * NN, cnt + (u0 + 0) * NN,
            csrs + (size_t)(u0 + 2) * EE, csrw + (size_t)(u0 + 2) * EE,
            base + (u0 + 2) * NN, cnt + (u0 + 2) * NN,
            rin + (c * 4 + 0) * NN, rin + (c * 4 + 2) * NN,
            b2 + (c * 4 + 0) * OUT_F, b2 + (c * 4 + 2) * OUT_F,
            zd, ci * OUT_F);
        k_gag2<<<gblocks, T>>>(
            y + (size_t)1 * NN * OUT_F, y + (size_t)3 * NN * OUT_F,
            csrs + (size_t)(u0 + 1) * EE, csrw + (size_t)(u0 + 1) * EE,
            base + (u0 + 1) * NN, cnt + (u0 + 1) * NN,
            csrs + (size_t)(u0 + 3) * EE, csrw + (size_t)(u0 + 3) * EE,
            base + (u0 + 3) * NN, cnt + (u0 + 3) * NN,
            rin + (c * 4 + 1) * NN, rin + (c * 4 + 3) * NN,
            b2 + (c * 4 + 1) * OUT_F, b2 + (c * 4 + 3) * OUT_F,
            zp, ci * OUT_F);
    }

    // ---- semantic attention ----
    const int rowsPT = NN * 3;
    k_split<<<(rowsPT * OUT_F / 4 + T - 1) / T, T>>>(zd, xd1, xd2, rowsPT * OUT_F / 4);
    k_split<<<(rowsPT * OUT_F / 4 + T - 1) / T, T>>>(zp, xp1, xp2, rowsPT * OUT_F / 4);

    float* Tbuf = y;
    const int amtiles = (rowsPT + 127) / 128;
    k_mma<OUT_F, OUT_F><<<dim3(OUT_F / 64, amtiles), 256>>>(
        xd1, xd2, xd1, xd2, wpa, wpb, Tbuf, rowsPT);
    k_mma<OUT_F, OUT_F><<<dim3(OUT_F / 64, amtiles), 256>>>(
        xp1, xp2, xp1, xp2, wpa, wpb, Tbuf + (size_t)rowsPT * OUT_F, rowsPT);

    k_zero<<<1, 32>>>(wsum, 8);
    int warps = 2 * NN * 3;
    k_wred<<<(warps * 32 + 255) / 256, 256>>>(Tbuf, bp, q, wsum);
    k_beta<<<1, 1>>>(wsum, beta, out + (size_t)2 * NN * OUT_F);
    k_combine<<<(2 * NN * OUT_F + T - 1) / T, T>>>(zd, zp, beta, out);
}

// round 6
// speedup vs baseline: 2.3597x; 1.2823x over previous
#include <cuda_runtime.h>
#include <cuda_bf16.h>
#include <cstdint>

#define NN 30000
#define EE 250000
#define IN_F 512
#define HID_F 256
#define OUT_F 128

typedef unsigned long long u64;
typedef __nv_bfloat16 bf16;

// ---------------- scratch (static device globals; no allocs) ----------------
__device__ float g_y[(size_t)12 * NN * HID_F];      // 12-rel GEMM outputs / attn T
__device__ float g_zd[(size_t)NN * 3 * OUT_F];
__device__ float g_zp[(size_t)NN * 3 * OUT_F];
__device__ float g_rout[12 * NN];
__device__ float g_rin[12 * NN];
__device__ float g_wsum[8];
__device__ float g_beta[8];
__device__ int   g_cnts[12 * NN];    // src histogram
__device__ int   g_cnt[12 * NN];     // dst histogram (CSR counts)
__device__ int   g_base[12 * NN];
__device__ int   g_cur[12 * NN];
__device__ int   g_csrs[(size_t)12 * EE];
__device__ float g_csrw[(size_t)12 * EE];
// bf16 split operands
__device__ __align__(16) bf16 g_x1[(size_t)2 * NN * IN_F];     // [xd, xp] hi
__device__ __align__(16) bf16 g_x2[(size_t)2 * NN * IN_F];     // lo
__device__ __align__(16) bf16 g_h1[(size_t)6 * NN * HID_F];    // [(ci,t)] hi
__device__ __align__(16) bf16 g_h2[(size_t)6 * NN * HID_F];
__device__ __align__(16) bf16 g_za1[(size_t)2 * NN * 3 * OUT_F];  // z splits hi
__device__ __align__(16) bf16 g_za2[(size_t)2 * NN * 3 * OUT_F];
__device__ __align__(16) bf16 g_wt1a[(size_t)12 * HID_F * IN_F];
__device__ __align__(16) bf16 g_wt1b[(size_t)12 * HID_F * IN_F];
__device__ __align__(16) bf16 g_wt2a[(size_t)12 * OUT_F * HID_F];
__device__ __align__(16) bf16 g_wt2b[(size_t)12 * OUT_F * HID_F];
__device__ __align__(16) bf16 g_wpa[(size_t)OUT_F * OUT_F];
__device__ __align__(16) bf16 g_wpb[(size_t)OUT_F * OUT_F];

__device__ __forceinline__ void fma4(float4& a, float w, const float4 v) {
    a.x += w * v.x; a.y += w * v.y; a.z += w * v.z; a.w += w * v.w;
}
__device__ __forceinline__ int u2cr(int u) {
    int ci = u >> 2;
    int c = (ci == 0) ? 0 : (ci == 1 ? 2 : 3);
    return c * 4 + (u & 3);
}

// ---------------- utility kernels ----------------
__global__ void k_zero(float* __restrict__ p, int n) {
    int i = blockIdx.x * blockDim.x + threadIdx.x;
    if (i < n) p[i] = 0.f;
}
__global__ void k_zeroi2(int* __restrict__ a, int* __restrict__ b, int n) {
    int i = blockIdx.x * blockDim.x + threadIdx.x;
    if (i < n) { a[i] = 0; b[i] = 0; }
}

__global__ void k_hist2(const int* __restrict__ src, const int* __restrict__ dst,
                        int* __restrict__ cnts, int* __restrict__ cntd) {
    int i = blockIdx.x * blockDim.x + threadIdx.x;
    if (i >= 12 * EE) return;
    int u = i / EE, e = i - u * EE;
    int cr = u2cr(u);
    atomicAdd(&cnts[u * NN + src[(size_t)cr * EE + e]], 1);
    atomicAdd(&cntd[u * NN + dst[(size_t)cr * EE + e]], 1);
}

__global__ void k_prep(const int* __restrict__ cnts, const int* __restrict__ cntd,
                       float* __restrict__ rout, float* __restrict__ rin) {
    int i = blockIdx.x * blockDim.x + threadIdx.x;
    if (i >= 12 * NN) return;
    rout[i] = rsqrtf((float)max(cnts[i], 1));
    rin[i]  = rsqrtf((float)max(cntd[i], 1));
}

// deterministic exclusive scan per u (12 blocks, 1024 threads)
__global__ void k_scan(const int* __restrict__ cnt, int* __restrict__ base,
                       int* __restrict__ cur) {
    __shared__ int ws[32];
    __shared__ int carry;
    int u = blockIdx.x;
    const int* c = cnt + u * NN;
    int* b = base + u * NN;
    int* q = cur + u * NN;
    int lane = threadIdx.x & 31, w = threadIdx.x >> 5;
    if (threadIdx.x == 0) carry = 0;
    __syncthreads();
    for (int off = 0; off < NN; off += 1024) {
        int i = off + threadIdx.x;
        int v = (i < NN) ? c[i] : 0;
        int s = v;
#pragma unroll
        for (int o = 1; o < 32; o <<= 1) {
            int t = __shfl_up_sync(0xffffffffu, s, o);
            if (lane >= o) s += t;
        }
        if (lane == 31) ws[w] = s;
        __syncthreads();
        if (w == 0) {
            int t2 = ws[lane];
#pragma unroll
            for (int o = 1; o < 32; o <<= 1) {
                int t = __shfl_up_sync(0xffffffffu, t2, o);
                if (lane >= o) t2 += t;
            }
            ws[lane] = t2;
        }
        __syncthreads();
        int excl = s - v + (w > 0 ? ws[w - 1] : 0) + carry;
        if (i < NN) { b[i] = excl; q[i] = excl; }
        __syncthreads();
        if (threadIdx.x == 1023) carry = excl + v;
        __syncthreads();
    }
}

__global__ void k_fill(const int* __restrict__ src, const int* __restrict__ dst,
                       const float* __restrict__ rout, int* __restrict__ cur,
                       int* __restrict__ csrs, float* __restrict__ csrw) {
    int i = blockIdx.x * blockDim.x + threadIdx.x;
    if (i >= 12 * EE) return;
    int u = i / EE, e = i - u * EE;
    int cr = u2cr(u);
    int s = src[(size_t)cr * EE + e];
    int d = dst[(size_t)cr * EE + e];
    int pos = atomicAdd(&cur[u * NN + d], 1);
    csrs[(size_t)u * EE + pos] = s;
    csrw[(size_t)u * EE + pos] = rout[u * NN + s];
}

// split fp32 -> bf16 hi/lo
__global__ void k_split(const float* __restrict__ x, bf16* __restrict__ hi,
                        bf16* __restrict__ lo, int n4) {
    int i = blockIdx.x * blockDim.x + threadIdx.x;
    if (i >= n4) return;
    float4 v = ((const float4*)x)[i];
    bf16 h0 = __float2bfloat16(v.x), h1 = __float2bfloat16(v.y);
    bf16 h2 = __float2bfloat16(v.z), h3 = __float2bfloat16(v.w);
    ((__nv_bfloat162*)hi)[2 * i]     = __halves2bfloat162(h0, h1);
    ((__nv_bfloat162*)hi)[2 * i + 1] = __halves2bfloat162(h2, h3);
    bf16 l0 = __float2bfloat16(v.x - __bfloat162float(h0));
    bf16 l1 = __float2bfloat16(v.y - __bfloat162float(h1));
    bf16 l2 = __float2bfloat16(v.z - __bfloat162float(h2));
    bf16 l3 = __float2bfloat16(v.w - __bfloat162float(h3));
    ((__nv_bfloat162*)lo)[2 * i]     = __halves2bfloat162(l0, l1);
    ((__nv_bfloat162*)lo)[2 * i + 1] = __halves2bfloat162(l2, l3);
}

// transpose+split weights: W [16][K][N] fp32 (channels 0,2,3) -> [12][N][K] bf16 hi/lo
__global__ void k_wts(const float* __restrict__ W, bf16* __restrict__ t1,
                      bf16* __restrict__ t2, int K, int N) {
    __shared__ float tile[32][33];
    int z = blockIdx.z;
    int cz = z >> 2;
    int c = (cz == 0) ? 0 : (cz == 1 ? 2 : 3);
    const float* Wm = W + (size_t)(c * 4 + (z & 3)) * K * N;
    bf16* o1 = t1 + (size_t)z * K * N;
    bf16* o2 = t2 + (size_t)z * K * N;
    int k0 = blockIdx.y * 32, n0 = blockIdx.x * 32;
    for (int r = threadIdx.y; r < 32; r += 8)
        tile[r][threadIdx.x] = Wm[(size_t)(k0 + r) * N + n0 + threadIdx.x];
    __syncthreads();
    for (int r = threadIdx.y; r < 32; r += 8) {
        float v = tile[threadIdx.x][r];
        bf16 h = __float2bfloat16(v);
        size_t o = (size_t)(n0 + r) * K + k0 + threadIdx.x;
        o1[o] = h;
        o2[o] = __float2bfloat16(v - __bfloat162float(h));
    }
}

__global__ void k_wts1(const float* __restrict__ W, bf16* __restrict__ t1,
                       bf16* __restrict__ t2, int K, int N) {
    __shared__ float tile[32][33];
    int k0 = blockIdx.y * 32, n0 = blockIdx.x * 32;
    for (int r = threadIdx.y; r < 32; r += 8)
        tile[r][threadIdx.x] = W[(size_t)(k0 + r) * N + n0 + threadIdx.x];
    __syncthreads();
    for (int r = threadIdx.y; r < 32; r += 8) {
        float v = tile[threadIdx.x][r];
        bf16 h = __float2bfloat16(v);
        size_t o = (size_t)(n0 + r) * K + k0 + threadIdx.x;
        t1[o] = h;
        t2[o] = __float2bfloat16(v - __bfloat162float(h));
    }
}

// ---------------- mma.sync bf16 GEMM, 128x128 tile, 3-chain split ----------------
// CH=1: A indexed per (channel, type); CH=0: A indexed per type only.
__device__ __forceinline__ void mma16816(float* c, const uint32_t* a, const uint32_t* b) {
    asm volatile("mma.sync.aligned.m16n8k16.row.col.f32.bf16.bf16.f32 "
                 "{%0,%1,%2,%3}, {%4,%5,%6,%7}, {%8,%9}, {%0,%1,%2,%3};"
                 : "+f"(c[0]), "+f"(c[1]), "+f"(c[2]), "+f"(c[3])
                 : "r"(a[0]), "r"(a[1]), "r"(a[2]), "r"(a[3]), "r"(b[0]), "r"(b[1]));
}

template <int KK, int NOUT, int CH>
__global__ void __launch_bounds__(256, 2) k_mma(
    const bf16* __restrict__ A1b, const bf16* __restrict__ A2b,
    const bf16* __restrict__ Bt1, const bf16* __restrict__ Bt2,
    float* __restrict__ Y, int M) {
    __shared__ uint32_t AS[2][2048];   // 128 x 32 bf16
    __shared__ uint32_t BS[2][2048];   // 128 x 32 bf16

    const int tid = threadIdx.x;
    const int lane = tid & 31;
    const int wid = tid >> 5;
    const int warpM = wid & 3;
    const int warpN = wid >> 2;        // 0..1
    constexpr int NT = NOUT / 128;
    const int u = blockIdx.x / NT;
    const int bn = (blockIdx.x % NT) * 128;
    const int bm = blockIdx.y * 128;

    const int aoff = (CH ? (u >> 2) * 2 : 0) + ((u & 3) >> 1);
    const bf16* A1 = A1b + (size_t)aoff * M * KK;
    const bf16* A2 = A2b + (size_t)aoff * M * KK;
    const bf16* B1 = Bt1 + (size_t)u * KK * NOUT;
    const bf16* B2 = Bt2 + (size_t)u * KK * NOUT;
    float* Yp = Y + (size_t)u * M * NOUT;

    const bf16* APass[3] = {A1, A1, A2};
    const bf16* BPass[3] = {B1, B2, B1};

    constexpr int CPP = KK / 32;
    constexpr int NC = 3 * CPP;

    float c[2][8][4];
#pragma unroll
    for (int i = 0; i < 2; ++i)
#pragma unroll
        for (int j = 0; j < 8; ++j)
#pragma unroll
            for (int l = 0; l < 4; ++l) c[i][j][l] = 0.f;

    uint4 va[2], vb[2];
    {
        const bf16* Ag = APass[0];
        const bf16* Bg = BPass[0];
#pragma unroll
        for (int i = 0; i < 2; ++i) {
            int u2 = tid + i * 256;
            int m = u2 >> 2, seg = u2 & 3;
            int gm = bm + m;
            va[i] = make_uint4(0, 0, 0, 0);
            if (gm < M)
                va[i] = *(const uint4*)(Ag + (size_t)gm * KK + (seg >> 1) * 16 + (seg & 1) * 8);
            int n = u2 >> 2;
            vb[i] = *(const uint4*)(Bg + (size_t)(bn + n) * KK + (seg >> 1) * 16 + (seg & 1) * 8);
        }
    }

#pragma unroll 1
    for (int g = 0; g < NC; ++g) {
        const int buf = g & 1;
#pragma unroll
        for (int i = 0; i < 2; ++i) {
            int u2 = tid + i * 256;
            int m = u2 >> 2, seg = u2 & 3;
            int kb = seg >> 1, h = seg & 1;
            int r = ((m >> 3) & 1) + 2 * h;
            int Lb = (((m & 7) * 4) + seg * 8) & 31;
            int W = ((kb * 8 + (m >> 4)) * 4 + r) * 32 + Lb;
            *(uint4*)&AS[buf][W] = va[i];
            int n = m;
            int Wb = ((kb * 16 + (n >> 3)) * 2 + h) * 32 + Lb;
            *(uint4*)&BS[buf][Wb] = vb[i];
        }
        __syncthreads();

        if (g + 1 < NC) {
            int pass = (g + 1) / CPP, kc = (g + 1) % CPP;
            const bf16* Ag = APass[pass];
            const bf16* Bg = BPass[pass];
            int koff = kc * 32;
#pragma unroll
            for (int i = 0; i < 2; ++i) {
                int u2 = tid + i * 256;
                int m = u2 >> 2, seg = u2 & 3;
                int gm = bm + m;
                va[i] = make_uint4(0, 0, 0, 0);
                if (gm < M)
                    va[i] = *(const uint4*)(Ag + (size_t)gm * KK + koff +
                                            (seg >> 1) * 16 + (seg & 1) * 8);
                vb[i] = *(const uint4*)(Bg + (size_t)(bn + m) * KK + koff +
                                        (seg >> 1) * 16 + (seg & 1) * 8);
            }
        }

#pragma unroll
        for (int kb = 0; kb < 2; ++kb) {
            uint32_t a[2][4], b[8][2];
#pragma unroll
            for (int mbl = 0; mbl < 2; ++mbl) {
                int mb = warpM * 2 + mbl;
#pragma unroll
                for (int r = 0; r < 4; ++r) {
                    int Lr = (lane + (kb * 2 + (r >> 1)) * 8) & 31;
                    a[mbl][r] = AS[buf][((kb * 8 + mb) * 4 + r) * 32 + Lr];
                }
            }
#pragma unroll
            for (int nbl = 0; nbl < 8; ++nbl) {
                int nb = warpN * 8 + nbl;
#pragma unroll
                for (int h = 0; h < 2; ++h) {
                    int Lr = (lane + (kb * 2 + h) * 8) & 31;
                    b[nbl][h] = BS[buf][((kb * 16 + nb) * 2 + h) * 32 + Lr];
                }
            }
#pragma unroll
            for (int mbl = 0; mbl < 2; ++mbl)
#pragma unroll
                for (int nbl = 0; nbl < 8; ++nbl)
                    mma16816(c[mbl][nbl], a[mbl], b[nbl]);
        }
        __syncthreads();
    }

#pragma unroll
    for (int mbl = 0; mbl < 2; ++mbl) {
        int mrow = bm + warpM * 32 + mbl * 16 + (lane >> 2);
#pragma unroll
        for (int nbl = 0; nbl < 8; ++nbl) {
            int ncol = bn + warpN * 64 + nbl * 8 + (lane & 3) * 2;
            float* base = Yp + (size_t)mrow * NOUT + ncol;
            if (mrow < M)
                *(float2*)base = make_float2(c[mbl][nbl][0], c[mbl][nbl][1]);
            if (mrow + 8 < M)
                *(float2*)(base + (size_t)8 * NOUT) = make_float2(c[mbl][nbl][2], c[mbl][nbl][3]);
        }
    }
}

// --------- fused gather layer1 (all 3 channels x 2 types via blockIdx.y) ---------
__global__ void __launch_bounds__(256) k_gag1(
    const float* __restrict__ y,
    const int* __restrict__ csrs, const float* __restrict__ csrw,
    const int* __restrict__ base, const int* __restrict__ cnt,
    const float* __restrict__ rin, const float* __restrict__ b1,
    bf16* __restrict__ h1, bf16* __restrict__ h2) {
    int gw = (blockIdx.x * blockDim.x + threadIdx.x) >> 5;
    if (gw >= NN) return;
    int lane = threadIdx.x & 31;
    int d = gw;
    int by = blockIdx.y;              // ci*2 + t
    int ci = by >> 1, t = by & 1;
    int uLo = ci * 4 + t, uHi = uLo + 2;
    int c = (ci == 0) ? 0 : (ci == 1 ? 2 : 3);
    const float* yLo = y + (size_t)uLo * NN * HID_F;
    const float* yHi = y + (size_t)uHi * NN * HID_F;
    const float* bLo = b1 + (c * 4 + t) * HID_F;
    const float* bHi = b1 + (c * 4 + t + 2) * HID_F;

    float4 a0 = make_float4(0, 0, 0, 0), a1 = a0, c0 = a0, c1 = a0;
    {
        int b = base[uLo * NN + d], n = cnt[uLo * NN + d];
        const int* cs = csrs + (size_t)uLo * EE;
        const float* cw = csrw + (size_t)uLo * EE;
        for (int i = 0; i < n; ++i) {
            int s = cs[b + i];
            float w = cw[b + i];
            const float4* r = (const float4*)(yLo + (size_t)s * HID_F);
            fma4(a0, w, r[lane]);
            fma4(a1, w, r[32 + lane]);
        }
    }
    {
        int b = base[uHi * NN + d], n = cnt[uHi * NN + d];
        const int* cs = csrs + (size_t)uHi * EE;
        const float* cw = csrw + (size_t)uHi * EE;
        for (int i = 0; i < n; ++i) {
            int s = cs[b + i];
            float w = cw[b + i];
            const float4* r = (const float4*)(yHi + (size_t)s * HID_F);
            fma4(c0, w, r[lane]);
            fma4(c1, w, r[32 + lane]);
        }
    }
    float rl = rin[uLo * NN + d], rh = rin[uHi * NN + d];
    bf16* o1 = h1 + (size_t)by * NN * HID_F;
    bf16* o2 = h2 + (size_t)by * NN * HID_F;
#pragma unroll
    for (int ch = 0; ch < 2; ++ch) {
        float4 A = ch ? a1 : a0, C = ch ? c1 : c0;
        float4 x = ((const float4*)bLo)[ch * 32 + lane];
        float4 yb = ((const float4*)bHi)[ch * 32 + lane];
        float r0 = fmaxf(x.x + yb.x + rl * A.x + rh * C.x, 0.f);
        float r1 = fmaxf(x.y + yb.y + rl * A.y + rh * C.y, 0.f);
        float r2 = fmaxf(x.z + yb.z + rl * A.z + rh * C.z, 0.f);
        float r3 = fmaxf(x.w + yb.w + rl * A.w + rh * C.w, 0.f);
        bf16 h0 = __float2bfloat16(r0), hh1 = __float2bfloat16(r1);
        bf16 h2v = __float2bfloat16(r2), h3 = __float2bfloat16(r3);
        __nv_bfloat162 p0 = __halves2bfloat162(h0, hh1);
        __nv_bfloat162 p1 = __halves2bfloat162(h2v, h3);
        uint2 st;
        st.x = *(unsigned*)&p0; st.y = *(unsigned*)&p1;
        size_t off = (size_t)d * HID_F + ch * 128 + lane * 4;
        *(uint2*)(o1 + off) = st;
        bf16 l0 = __float2bfloat16(r0 - __bfloat162float(h0));
        bf16 l1 = __float2bfloat16(r1 - __bfloat162float(hh1));
        bf16 l2 = __float2bfloat16(r2 - __bfloat162float(h2v));
        bf16 l3 = __float2bfloat16(r3 - __bfloat162float(h3));
        p0 = __halves2bfloat162(l0, l1);
        p1 = __halves2bfloat162(l2, l3);
        st.x = *(unsigned*)&p0; st.y = *(unsigned*)&p1;
        *(uint2*)(o2 + off) = st;
    }
}

// --------- fused gather layer2: z slice + bf16 split of z ---------
__global__ void __launch_bounds__(256) k_gag2(
    const float* __restrict__ y,
    const int* __restrict__ csrs, const float* __restrict__ csrw,
    const int* __restrict__ base, const int* __restrict__ cnt,
    const float* __restrict__ rin, const float* __restrict__ b2,
    float* __restrict__ zd, float* __restrict__ zp,
    bf16* __restrict__ za1, bf16* __restrict__ za2) {
    int gw = (blockIdx.x * blockDim.x + threadIdx.x) >> 5;
    if (gw >= NN) return;
    int lane = threadIdx.x & 31;
    int d = gw;
    int by = blockIdx.y;
    int ci = by >> 1, t = by & 1;
    int uLo = ci * 4 + t, uHi = uLo + 2;
    int c = (ci == 0) ? 0 : (ci == 1 ? 2 : 3);
    const float* yLo = y + (size_t)uLo * NN * OUT_F;
    const float* yHi = y + (size_t)uHi * NN * OUT_F;
    const float* bLo = b2 + (c * 4 + t) * OUT_F;
    const float* bHi = b2 + (c * 4 + t + 2) * OUT_F;

    float4 a0 = make_float4(0, 0, 0, 0), c0 = a0;
    {
        int b = base[uLo * NN + d], n = cnt[uLo * NN + d];
        const int* cs = csrs + (size_t)uLo * EE;
        const float* cw = csrw + (size_t)uLo * EE;
        for (int i = 0; i < n; ++i)
            fma4(a0, cw[b + i], ((const float4*)(yLo + (size_t)cs[b + i] * OUT_F))[lane]);
    }
    {
        int b = base[uHi * NN + d], n = cnt[uHi * NN + d];
        const int* cs = csrs + (size_t)uHi * EE;
        const float* cw = csrw + (size_t)uHi * EE;
        for (int i = 0; i < n; ++i)
            fma4(c0, cw[b + i], ((const float4*)(yHi + (size_t)cs[b + i] * OUT_F))[lane]);
    }
    float rl = rin[uLo * NN + d], rh = rin[uHi * NN + d];
    float4 x = ((const float4*)bLo)[lane], yb = ((const float4*)bHi)[lane];
    float4 res;
    res.x = fmaxf(x.x + yb.x + rl * a0.x + rh * c0.x, 0.f);
    res.y = fmaxf(x.y + yb.y + rl * a0.y + rh * c0.y, 0.f);
    res.z = fmaxf(x.z + yb.z + rl * a0.z + rh * c0.z, 0.f);
    res.w = fmaxf(x.w + yb.w + rl * a0.w + rh * c0.w, 0.f);
    float* zt = t ? zp : zd;
    *(float4*)(zt + (size_t)d * (3 * OUT_F) + ci * OUT_F + lane * 4) = res;

    // bf16 split for attention GEMM: row = t*NN*3 + d*3 + ci
    size_t row = (size_t)t * NN * 3 + (size_t)d * 3 + ci;
    bf16 h0 = __float2bfloat16(res.x), h1 = __float2bfloat16(res.y);
    bf16 h2 = __float2bfloat16(res.z), h3 = __float2bfloat16(res.w);
    __nv_bfloat162 p0 = __halves2bfloat162(h0, h1);
    __nv_bfloat162 p1 = __halves2bfloat162(h2, h3);
    uint2 st;
    st.x = *(unsigned*)&p0; st.y = *(unsigned*)&p1;
    *(uint2*)(za1 + row * OUT_F + lane * 4) = st;
    bf16 l0 = __float2bfloat16(res.x - __bfloat162float(h0));
    bf16 l1 = __float2bfloat16(res.y - __bfloat162float(h1));
    bf16 l2 = __float2bfloat16(res.z - __bfloat162float(h2));
    bf16 l3 = __float2bfloat16(res.w - __bfloat162float(h3));
    p0 = __halves2bfloat162(l0, l1);
    p1 = __halves2bfloat162(l2, l3);
    st.x = *(unsigned*)&p0; st.y = *(unsigned*)&p1;
    *(uint2*)(za2 + row * OUT_F + lane * 4) = st;
}

// ------------- attention tail -------------
__global__ void k_wred(const float* __restrict__ T, const float* __restrict__ bp,
                       const float* __restrict__ q, float* __restrict__ wsum) {
    __shared__ float sb[6];
    if (threadIdx.x < 6) sb[threadIdx.x] = 0.f;
    __syncthreads();
    int gw = (blockIdx.x * blockDim.x + threadIdx.x) >> 5;
    int lane = threadIdx.x & 31;
    bool valid = gw < 2 * NN * 3;
    float s = 0.f;
    int t = 0, k = 0;
    if (valid) {
        t = gw / (NN * 3);
        int r = gw - t * NN * 3;
        k = r % 3;
        const float* tp = T + (size_t)gw * OUT_F;
        int j0 = lane * 4;
        float4 tv = *(const float4*)(tp + j0);
        float4 bv = *(const float4*)(bp + j0);
        float4 qv = *(const float4*)(q + j0);
        s = tanhf(tv.x + bv.x) * qv.x + tanhf(tv.y + bv.y) * qv.y
          + tanhf(tv.z + bv.z) * qv.z + tanhf(tv.w + bv.w) * qv.w;
    }
#pragma unroll
    for (int o = 16; o; o >>= 1) s += __shfl_down_sync(0xffffffffu, s, o);
    if (valid && lane == 0) atomicAdd(&sb[t * 3 + k], s);
    __syncthreads();
    if (threadIdx.x < 6 && sb[threadIdx.x] != 0.f) atomicAdd(&wsum[threadIdx.x], sb[threadIdx.x]);
}

__global__ void k_beta(const float* __restrict__ wsum, float* __restrict__ beta,
                       float* __restrict__ outBeta) {
    if (threadIdx.x != 0 || blockIdx.x != 0) return;
    for (int t = 0; t < 2; ++t) {
        float w0 = wsum[t * 3 + 0] / (float)NN;
        float w1 = wsum[t * 3 + 1] / (float)NN;
        float w2 = wsum[t * 3 + 2] / (float)NN;
        float m = fmaxf(w0, fmaxf(w1, w2));
        float e0 = expf(w0 - m), e1 = expf(w1 - m), e2 = expf(w2 - m);
        float inv = 1.f / (e0 + e1 + e2);
        beta[t * 3 + 0] = e0 * inv; outBeta[t * 3 + 0] = e0 * inv;
        beta[t * 3 + 1] = e1 * inv; outBeta[t * 3 + 1] = e1 * inv;
        beta[t * 3 + 2] = e2 * inv; outBeta[t * 3 + 2] = e2 * inv;
    }
}

__global__ void k_combine(const float* __restrict__ zd, const float* __restrict__ zp,
                          const float* __restrict__ beta, float* __restrict__ out) {
    int i = blockIdx.x * blockDim.x + threadIdx.x;
    if (i >= 2 * NN * OUT_F) return;
    int t = i / (NN * OUT_F);
    int r = i - t * NN * OUT_F;
    int n = r / OUT_F, f = r - n * OUT_F;
    const float* z = (t ? zp : zd) + (size_t)n * (3 * OUT_F) + f;
    const float* b = beta + t * 3;
    out[i] = b[0] * z[0] + b[1] * z[OUT_F] + b[2] * z[2 * OUT_F];
}

// ---------------- host orchestration ----------------
extern "C" void kernel_launch(void* const* d_in, const int* in_sizes, int n_in,
                              void* d_out, int out_size) {
    const float* xd  = (const float*)d_in[0];
    const float* xp  = (const float*)d_in[1];
    const int*   src = (const int*)  d_in[2];
    const int*   dst = (const int*)  d_in[3];
    const float* W1  = (const float*)d_in[4];
    const float* b1  = (const float*)d_in[5];
    const float* W2  = (const float*)d_in[6];
    const float* b2  = (const float*)d_in[7];
    const float* Wpm = (const float*)d_in[8];
    const float* bp  = (const float*)d_in[9];
    const float* q   = (const float*)d_in[10];
    float* out = (float*)d_out;

    float *y, *zd, *zp, *rout, *rin, *wsum, *beta, *csrw;
    int *cnts, *cnt, *base, *cur, *csrs;
    bf16 *x1, *x2, *h1, *h2, *za1, *za2;
    bf16 *wt1a, *wt1b, *wt2a, *wt2b, *wpa, *wpb;
    cudaGetSymbolAddress((void**)&y,    g_y);
    cudaGetSymbolAddress((void**)&zd,   g_zd);
    cudaGetSymbolAddress((void**)&zp,   g_zp);
    cudaGetSymbolAddress((void**)&rout, g_rout);
    cudaGetSymbolAddress((void**)&rin,  g_rin);
    cudaGetSymbolAddress((void**)&wsum, g_wsum);
    cudaGetSymbolAddress((void**)&beta, g_beta);
    cudaGetSymbolAddress((void**)&cnts, g_cnts);
    cudaGetSymbolAddress((void**)&cnt,  g_cnt);
    cudaGetSymbolAddress((void**)&base, g_base);
    cudaGetSymbolAddress((void**)&cur,  g_cur);
    cudaGetSymbolAddress((void**)&csrs, g_csrs);
    cudaGetSymbolAddress((void**)&csrw, g_csrw);
    cudaGetSymbolAddress((void**)&x1,   g_x1);
    cudaGetSymbolAddress((void**)&x2,   g_x2);
    cudaGetSymbolAddress((void**)&h1,   g_h1);
    cudaGetSymbolAddress((void**)&h2,   g_h2);
    cudaGetSymbolAddress((void**)&za1,  g_za1);
    cudaGetSymbolAddress((void**)&za2,  g_za2);
    cudaGetSymbolAddress((void**)&wt1a, g_wt1a);
    cudaGetSymbolAddress((void**)&wt1b, g_wt1b);
    cudaGetSymbolAddress((void**)&wt2a, g_wt2a);
    cudaGetSymbolAddress((void**)&wt2b, g_wt2b);
    cudaGetSymbolAddress((void**)&wpa,  g_wpa);
    cudaGetSymbolAddress((void**)&wpb,  g_wpb);

    const int T = 256;
    const int mtiles = (NN + 127) / 128;            // 235
    const int gblocks = (NN * 32 + T - 1) / T;      // 3750

    // 1-3: splits + W1 transform (k_mma is then launch #4 for ncu -s 5 -c 1)
    k_split<<<(NN * IN_F / 4 + T - 1) / T, T>>>(xd, x1, x2, NN * IN_F / 4);
    k_split<<<(NN * IN_F / 4 + T - 1) / T, T>>>(xp, x1 + (size_t)NN * IN_F,
                                                x2 + (size_t)NN * IN_F, NN * IN_F / 4);
    k_wts<<<dim3(HID_F / 32, IN_F / 32, 12), dim3(32, 8)>>>(W1, wt1a, wt1b, IN_F, HID_F);

    // 4: ALL 12 layer-1 GEMMs in one launch
    k_mma<IN_F, HID_F, 0><<<dim3(12 * (HID_F / 128), mtiles), 256>>>(
        x1, x2, wt1a, wt1b, y, NN);

    // CSR + remaining weight transforms (overlap-ish; ordered after for profiling)
    k_zeroi2<<<(12 * NN + T - 1) / T, T>>>(cnts, cnt, 12 * NN);
    k_hist2<<<(12 * EE + T - 1) / T, T>>>(src, dst, cnts, cnt);
    k_prep<<<(12 * NN + T - 1) / T, T>>>(cnts, cnt, rout, rin);
    k_scan<<<12, 1024>>>(cnt, base, cur);
    k_fill<<<(12 * EE + T - 1) / T, T>>>(src, dst, rout, cur, csrs, csrw);
    k_wts<<<dim3(OUT_F / 32, HID_F / 32, 12), dim3(32, 8)>>>(W2, wt2a, wt2b, HID_F, OUT_F);
    k_wts1<<<dim3(OUT_F / 32, OUT_F / 32), dim3(32, 8)>>>(Wpm, wpa, wpb, OUT_F, OUT_F);

    // gather layer 1 (all channels/types)
    k_gag1<<<dim3(gblocks, 6), T>>>(y, csrs, csrw, base, cnt, rin, b1, h1, h2);

    // ALL 12 layer-2 GEMMs
    k_mma<HID_F, OUT_F, 1><<<dim3(12, mtiles), 256>>>(h1, h2, wt2a, wt2b, y, NN);

    // gather layer 2 (+ z bf16 split)
    k_gag2<<<dim3(gblocks, 6), T>>>(y, csrs, csrw, base, cnt, rin, b2, zd, zp, za1, za2);

    // attention GEMM: both types in one launch, M = 180000
    const int rowsA = 2 * NN * 3;
    k_mma<OUT_F, OUT_F, 0><<<dim3(1, (rowsA + 127) / 128), 256>>>(
        za1, za2, wpa, wpb, y, rowsA);

    k_zero<<<1, 32>>>(wsum, 8);
    k_wred<<<(rowsA * 32 + 255) / 256, 256>>>(y, bp, q, wsum);
    k_beta<<<1, 1>>>(wsum, beta, out + (size_t)2 * NN * OUT_F);
    k_combine<<<(2 * NN * OUT_F + T - 1) / T, T>>>(zd, zp, beta, out);
}